// round 1
// baseline (speedup 1.0000x reference)
#include <cuda_runtime.h>
#include <math.h>

#define BB 8192
#define TT 128
#define DD 7
#define II 128
#define CC 10
#define HH 64
#define LL 128
#define NCOL (TT*DD)   // 896
#define NG 8           // tree groups
#define TPG (TT/NG)    // 16 trees per group

// Scratch (device globals: allocation-free rule)
__device__ __align__(16) float g_s[(size_t)NCOL*BB];      // s[col][b], col=t*7+d  (29.4 MB)
__device__ __align__(16) float g_attn[(size_t)TT*BB];     // attn[t][b]            (4.2 MB)
__device__ __align__(16) float g_lp[TT*LL*12];            // leaf softmax, C padded to 12
__device__ __align__(16) float g_partial[(size_t)NG*BB*CC];

// ---------------------------------------------------------------------------
// Kernel 1: leaf softmax over C (tiny, data-independent of x)
// ---------------------------------------------------------------------------
__global__ void k_leafsm(const float* __restrict__ leaf) {
    int row = blockIdx.x * 256 + threadIdx.x;   // t*L + l, 16384 rows
    if (row >= TT * LL) return;
    const float* in = leaf + (size_t)row * CC;
    float m = in[0];
#pragma unroll
    for (int c = 1; c < CC; c++) m = fmaxf(m, in[c]);
    float e[CC]; float sum = 0.f;
#pragma unroll
    for (int c = 0; c < CC; c++) { e[c] = __expf(in[c] - m); sum += e[c]; }
    float inv = __fdividef(1.f, sum);
    float* o = g_lp + (size_t)row * 12;
#pragma unroll
    for (int c = 0; c < CC; c++) o[c] = e[c] * inv;
    o[10] = 0.f; o[11] = 0.f;
}

// ---------------------------------------------------------------------------
// Kernel 2: z = x @ FM^T - th, s = 0.5*(z/(1+|z|)+1)  -> g_s[col][b]
// GEMM-NT  M=8192, N=896, K=128.  Tile 128x128, BK=32, 8x8 per thread.
// ---------------------------------------------------------------------------
__global__ __launch_bounds__(256) void k_zs(const float* __restrict__ x,
                                            const float* __restrict__ fm,
                                            const float* __restrict__ th) {
    __shared__ float As[32][128];   // As[k][m]
    __shared__ float Bs[32][128];   // Bs[k][n]
    int tid = threadIdx.x;
    int bm = blockIdx.x * 128;
    int bn = blockIdx.y * 128;
    int tm = (tid >> 4) * 8;
    int tn = (tid & 15) * 8;
    float acc[8][8];
#pragma unroll
    for (int i = 0; i < 8; i++)
#pragma unroll
        for (int j = 0; j < 8; j++) acc[i][j] = 0.f;

    for (int kc = 0; kc < 128; kc += 32) {
#pragma unroll
        for (int j = 0; j < 4; j++) {
            int fl = tid + 256 * j;           // 1024 float4 slots per operand
            int row = fl >> 3;
            int kq = (fl & 7) * 4;
            float4 v = *(const float4*)(x + (size_t)(bm + row) * 128 + kc + kq);
            As[kq + 0][row] = v.x; As[kq + 1][row] = v.y;
            As[kq + 2][row] = v.z; As[kq + 3][row] = v.w;
            float4 w = *(const float4*)(fm + (size_t)(bn + row) * 128 + kc + kq);
            Bs[kq + 0][row] = w.x; Bs[kq + 1][row] = w.y;
            Bs[kq + 2][row] = w.z; Bs[kq + 3][row] = w.w;
        }
        __syncthreads();
#pragma unroll
        for (int k = 0; k < 32; k++) {
            float4 a0 = *(const float4*)&As[k][tm];
            float4 a1 = *(const float4*)&As[k][tm + 4];
            float4 c0 = *(const float4*)&Bs[k][tn];
            float4 c1 = *(const float4*)&Bs[k][tn + 4];
            float av[8] = {a0.x, a0.y, a0.z, a0.w, a1.x, a1.y, a1.z, a1.w};
            float bv[8] = {c0.x, c0.y, c0.z, c0.w, c1.x, c1.y, c1.z, c1.w};
#pragma unroll
            for (int i = 0; i < 8; i++)
#pragma unroll
                for (int j = 0; j < 8; j++) acc[i][j] += av[i] * bv[j];
        }
        __syncthreads();
    }
#pragma unroll
    for (int i = 0; i < 8; i++) {
        int m = bm + tm + i;
#pragma unroll
        for (int j = 0; j < 8; j++) {
            int col = bn + tn + j;
            float z = acc[i][j] - __ldg(th + col);
            float s = 0.5f * (__fdividef(z, 1.0f + fabsf(z)) + 1.0f);
            g_s[(size_t)col * BB + m] = s;
        }
    }
}

// ---------------------------------------------------------------------------
// Kernel 3: attn = softmax(relu(x@W1+b1)@W2+b2)  -> g_attn[t][b]
// 256 threads, 32 batch rows per block.
// ---------------------------------------------------------------------------
__global__ __launch_bounds__(256) void k_attn(const float* __restrict__ x,
                                              const float* __restrict__ W1,
                                              const float* __restrict__ b1,
                                              const float* __restrict__ W2,
                                              const float* __restrict__ b2) {
    __shared__ float xst[128 * 32];   // x transposed [k][bl]
    __shared__ float hst[64 * 32];    // h transposed [k][bl]
    __shared__ float stage[128 * 33]; // W1/W2 chunks (<=4096 floats) and logits [t][bl] padded
    int tid = threadIdx.x;
    int b0 = blockIdx.x * 32;
    // phase 1: load x tile transposed
#pragma unroll
    for (int j = 0; j < 4; j++) {
        int idx = tid + 256 * j;            // 1024 float4
        int bl = idx & 31;
        int kq = (idx >> 5) * 4;
        float4 v = *(const float4*)(x + (size_t)(b0 + bl) * 128 + kq);
        xst[(kq + 0) * 32 + bl] = v.x; xst[(kq + 1) * 32 + bl] = v.y;
        xst[(kq + 2) * 32 + bl] = v.z; xst[(kq + 3) * 32 + bl] = v.w;
    }
    int bl = tid & 31;
    int grp = tid >> 5;   // warp id, 0..7
    // phase 2: h = relu(x@W1+b1), each thread 8 h-values
    float hacc[8];
#pragma unroll
    for (int j = 0; j < 8; j++) hacc[j] = 0.f;
    for (int kc = 0; kc < 128; kc += 64) {
        __syncthreads();
#pragma unroll
        for (int j = 0; j < 4; j++) {
            int idx = tid + 256 * j;        // 4096 floats of W1 chunk
            ((float4*)stage)[idx] = *((const float4*)(W1 + (size_t)kc * 64) + idx);
        }
        __syncthreads();
#pragma unroll 8
        for (int k = 0; k < 64; k++) {
            float xv = xst[(kc + k) * 32 + bl];
            float4 w0 = *(const float4*)&stage[k * 64 + grp * 8];
            float4 w1 = *(const float4*)&stage[k * 64 + grp * 8 + 4];
            hacc[0] += xv * w0.x; hacc[1] += xv * w0.y;
            hacc[2] += xv * w0.z; hacc[3] += xv * w0.w;
            hacc[4] += xv * w1.x; hacc[5] += xv * w1.y;
            hacc[6] += xv * w1.z; hacc[7] += xv * w1.w;
        }
    }
#pragma unroll
    for (int jj = 0; jj < 8; jj++) {
        float h = hacc[jj] + __ldg(b1 + grp * 8 + jj);
        hst[(grp * 8 + jj) * 32 + bl] = fmaxf(h, 0.f);
    }
    // phase 3: logits = h@W2+b2, each thread 16 t-values
    float lacc[16];
#pragma unroll
    for (int j = 0; j < 16; j++) lacc[j] = 0.f;
    for (int kc = 0; kc < 64; kc += 32) {
        __syncthreads();
#pragma unroll
        for (int j = 0; j < 4; j++) {
            int idx = tid + 256 * j;        // 4096 floats of W2 chunk
            ((float4*)stage)[idx] = *((const float4*)(W2 + (size_t)kc * 128) + idx);
        }
        __syncthreads();
#pragma unroll 4
        for (int k = 0; k < 32; k++) {
            float hv = hst[(kc + k) * 32 + bl];
            const float4* wr = (const float4*)&stage[k * 128 + grp * 16];
            float4 w0 = wr[0], w1 = wr[1], w2 = wr[2], w3 = wr[3];
            lacc[0]  += hv * w0.x; lacc[1]  += hv * w0.y; lacc[2]  += hv * w0.z; lacc[3]  += hv * w0.w;
            lacc[4]  += hv * w1.x; lacc[5]  += hv * w1.y; lacc[6]  += hv * w1.z; lacc[7]  += hv * w1.w;
            lacc[8]  += hv * w2.x; lacc[9]  += hv * w2.y; lacc[10] += hv * w2.z; lacc[11] += hv * w2.w;
            lacc[12] += hv * w3.x; lacc[13] += hv * w3.y; lacc[14] += hv * w3.z; lacc[15] += hv * w3.w;
        }
    }
    __syncthreads();
    // logits -> stage as ls[t*33 + bl] (padded: conflict-free both directions)
#pragma unroll
    for (int tt = 0; tt < 16; tt++)
        stage[(grp * 16 + tt) * 33 + bl] = lacc[tt] + __ldg(b2 + grp * 16 + tt);
    __syncthreads();
    // softmax over T=128: warp 'grp' handles rows grp*4..grp*4+3
    int lane = bl;
    for (int r4 = 0; r4 < 4; r4++) {
        int r = grp * 4 + r4;
        float v0 = stage[(lane +  0) * 33 + r];
        float v1 = stage[(lane + 32) * 33 + r];
        float v2 = stage[(lane + 64) * 33 + r];
        float v3 = stage[(lane + 96) * 33 + r];
        float m = fmaxf(fmaxf(v0, v1), fmaxf(v2, v3));
#pragma unroll
        for (int o = 16; o > 0; o >>= 1) m = fmaxf(m, __shfl_xor_sync(0xffffffffu, m, o));
        float e0 = __expf(v0 - m), e1 = __expf(v1 - m), e2 = __expf(v2 - m), e3 = __expf(v3 - m);
        float s = e0 + e1 + e2 + e3;
#pragma unroll
        for (int o = 16; o > 0; o >>= 1) s += __shfl_xor_sync(0xffffffffu, s, o);
        float inv = __fdividef(1.f, s);
        int gb = b0 + r;
        g_attn[(size_t)(lane +  0) * BB + gb] = e0 * inv;
        g_attn[(size_t)(lane + 32) * BB + gb] = e1 * inv;
        g_attn[(size_t)(lane + 64) * BB + gb] = e2 * inv;
        g_attn[(size_t)(lane + 96) * BB + gb] = e3 * inv;
    }
}

// ---------------------------------------------------------------------------
// Kernel 4: tree evaluation. Block = 256 b-rows x 16 trees (gridDim.y groups).
// p factorized into lo8 (bits 0-2) x hi16 (bits 3-6, pre-scaled by attn).
// ---------------------------------------------------------------------------
__global__ __launch_bounds__(256) void k_trees() {
    __shared__ float4 lp4[384];    // one tree's leaf probs: 128 leaves x 12 floats
    int tid = threadIdx.x;
    int b = blockIdx.x * 256 + tid;
    int tg = blockIdx.y;
    float acc[10];
#pragma unroll
    for (int c = 0; c < 10; c++) acc[c] = 0.f;

    for (int ti = 0; ti < TPG; ti++) {
        int t = tg * TPG + ti;
        __syncthreads();
        const float4* src = (const float4*)(g_lp + (size_t)t * LL * 12);
        for (int i = tid; i < 384; i += 256) lp4[i] = src[i];
        __syncthreads();

        const float* sp = g_s + (size_t)t * DD * BB + b;   // coalesced: lanes = consecutive b
        float s0 = sp[0],      s1 = sp[BB],     s2 = sp[2 * BB], s3 = sp[3 * BB];
        float s4 = sp[4 * BB], s5 = sp[5 * BB], s6 = sp[6 * BB];
        float a = g_attn[(size_t)t * BB + b];

        float lo8[8];
#pragma unroll
        for (int j = 0; j < 8; j++) {
            float v = (j & 1) ? (1.f - s0) : s0;
            v *= (j & 2) ? (1.f - s1) : s1;
            v *= (j & 4) ? (1.f - s2) : s2;
            lo8[j] = v;
        }
        float hi16[16];
#pragma unroll
        for (int j = 0; j < 16; j++) {
            float v = (j & 1) ? (1.f - s3) : s3;
            v *= (j & 2) ? (1.f - s4) : s4;
            v *= (j & 4) ? (1.f - s5) : s5;
            v *= (j & 8) ? (1.f - s6) : s6;
            hi16[j] = v * a;   // fold attention weight in here
        }
#pragma unroll 4
        for (int hi = 0; hi < 16; hi++) {
            float ph = hi16[hi];
            const float4* row = lp4 + hi * 24;
#pragma unroll
            for (int lo = 0; lo < 8; lo++) {
                float p = ph * lo8[lo];
                float4 c0 = row[lo * 3 + 0];
                float4 c1 = row[lo * 3 + 1];
                float4 c2 = row[lo * 3 + 2];
                acc[0] += p * c0.x; acc[1] += p * c0.y; acc[2] += p * c0.z; acc[3] += p * c0.w;
                acc[4] += p * c1.x; acc[5] += p * c1.y; acc[6] += p * c1.z; acc[7] += p * c1.w;
                acc[8] += p * c2.x; acc[9] += p * c2.y;
            }
        }
    }
    float* po = g_partial + ((size_t)tg * BB + b) * CC;
#pragma unroll
    for (int c = 0; c < CC; c++) po[c] = acc[c];
}

// ---------------------------------------------------------------------------
// Kernel 5: reduce NG partials -> output
// ---------------------------------------------------------------------------
__global__ void k_reduce(float* __restrict__ out) {
    int i = blockIdx.x * 256 + threadIdx.x;
    if (i < BB * CC) {
        float v = 0.f;
#pragma unroll
        for (int g = 0; g < NG; g++) v += g_partial[(size_t)g * BB * CC + i];
        out[i] = v;
    }
}

// ---------------------------------------------------------------------------
extern "C" void kernel_launch(void* const* d_in, const int* in_sizes, int n_in,
                              void* d_out, int out_size) {
    const float* x    = (const float*)d_in[0];
    const float* fm   = (const float*)d_in[1];
    const float* th   = (const float*)d_in[2];
    const float* leaf = (const float*)d_in[3];
    const float* W1   = (const float*)d_in[4];
    const float* b1   = (const float*)d_in[5];
    const float* W2   = (const float*)d_in[6];
    const float* b2   = (const float*)d_in[7];
    float* out = (float*)d_out;

    k_leafsm<<<64, 256>>>(leaf);
    k_zs<<<dim3(64, 7), 256>>>(x, fm, th);
    k_attn<<<256, 256>>>(x, W1, b1, W2, b2);
    k_trees<<<dim3(32, NG), 256>>>();
    k_reduce<<<320, 256>>>(out);
}

// round 2
// speedup vs baseline: 1.0085x; 1.0085x over previous
#include <cuda_runtime.h>
#include <math.h>

#define BB 8192
#define TT 128
#define DD 7
#define II 128
#define CC 10
#define HH 64
#define LL 128
#define NCOL (TT*DD)   // 896
#define NG 16          // tree groups
#define TPG (TT/NG)    // 8 trees per group

// Scratch (device globals: allocation-free rule)
__device__ __align__(16) float g_s[(size_t)NCOL*BB];      // s[col][b], col=t*7+d
__device__ __align__(16) float g_attn[(size_t)TT*BB];     // attn[t][b]
__device__ __align__(16) float g_lp[TT*LL*12];            // leaf softmax, C padded to 12
__device__ __align__(16) float g_partial[(size_t)NG*BB*CC];

// ---- packed fp32x2 helpers (full precision, 2 FMAs / instruction) ----------
__device__ __forceinline__ unsigned long long pk2(float lo, float hi) {
    unsigned long long r;
    asm("mov.b64 %0, {%1, %2};" : "=l"(r) : "f"(lo), "f"(hi));
    return r;
}
__device__ __forceinline__ void upk2(unsigned long long v, float& lo, float& hi) {
    asm("mov.b64 {%0, %1}, %2;" : "=f"(lo), "=f"(hi) : "l"(v));
}
__device__ __forceinline__ unsigned long long fma2(unsigned long long a,
                                                   unsigned long long b,
                                                   unsigned long long c) {
    unsigned long long d;
    asm("fma.rn.f32x2 %0, %1, %2, %3;" : "=l"(d) : "l"(a), "l"(b), "l"(c));
    return d;
}
__device__ __forceinline__ unsigned long long mul2(unsigned long long a,
                                                   unsigned long long b) {
    unsigned long long d;
    asm("mul.rn.f32x2 %0, %1, %2;" : "=l"(d) : "l"(a), "l"(b));
    return d;
}

// ---------------------------------------------------------------------------
// Kernel 1: leaf softmax over C
// ---------------------------------------------------------------------------
__global__ void k_leafsm(const float* __restrict__ leaf) {
    int row = blockIdx.x * 256 + threadIdx.x;   // t*L + l, 16384 rows
    if (row >= TT * LL) return;
    const float* in = leaf + (size_t)row * CC;
    float m = in[0];
#pragma unroll
    for (int c = 1; c < CC; c++) m = fmaxf(m, in[c]);
    float e[CC]; float sum = 0.f;
#pragma unroll
    for (int c = 0; c < CC; c++) { e[c] = __expf(in[c] - m); sum += e[c]; }
    float inv = __fdividef(1.f, sum);
    float* o = g_lp + (size_t)row * 12;
#pragma unroll
    for (int c = 0; c < CC; c++) o[c] = e[c] * inv;
    o[10] = 0.f; o[11] = 0.f;
}

// ---------------------------------------------------------------------------
// Kernel 2: z = x @ FM^T - th, s = 0.5*(z/(1+|z|)+1)  -> g_s[col][b]
// GEMM-NT  M=8192, N=896, K=128.  Tile 128x128, BK=32, 8x8/thread, f32x2.
// ---------------------------------------------------------------------------
__global__ __launch_bounds__(256) void k_zs(const float* __restrict__ x,
                                            const float* __restrict__ fm,
                                            const float* __restrict__ th) {
    __shared__ __align__(16) float As[32][128];   // As[k][m]
    __shared__ __align__(16) float Bs[32][128];   // Bs[k][n]
    int tid = threadIdx.x;
    int bm = blockIdx.x * 128;
    int bn = blockIdx.y * 128;
    int tm = (tid >> 4) * 8;
    int tn = (tid & 15) * 8;
    unsigned long long acc2[8][4];
#pragma unroll
    for (int i = 0; i < 8; i++)
#pragma unroll
        for (int j = 0; j < 4; j++) acc2[i][j] = 0ull;

    for (int kc = 0; kc < 128; kc += 32) {
#pragma unroll
        for (int j = 0; j < 4; j++) {
            int fl = tid + 256 * j;           // 1024 float4 slots per operand
            int row = fl >> 3;
            int kq = (fl & 7) * 4;
            float4 v = *(const float4*)(x + (size_t)(bm + row) * 128 + kc + kq);
            As[kq + 0][row] = v.x; As[kq + 1][row] = v.y;
            As[kq + 2][row] = v.z; As[kq + 3][row] = v.w;
            float4 w = *(const float4*)(fm + (size_t)(bn + row) * 128 + kc + kq);
            Bs[kq + 0][row] = w.x; Bs[kq + 1][row] = w.y;
            Bs[kq + 2][row] = w.z; Bs[kq + 3][row] = w.w;
        }
        __syncthreads();
#pragma unroll
        for (int k = 0; k < 32; k++) {
            float4 a0 = *(const float4*)&As[k][tm];
            float4 a1 = *(const float4*)&As[k][tm + 4];
            ulonglong2 bq0 = *(const ulonglong2*)&Bs[k][tn];
            ulonglong2 bq1 = *(const ulonglong2*)&Bs[k][tn + 4];
            unsigned long long bp[4] = {bq0.x, bq0.y, bq1.x, bq1.y};
            float av[8] = {a0.x, a0.y, a0.z, a0.w, a1.x, a1.y, a1.z, a1.w};
#pragma unroll
            for (int i = 0; i < 8; i++) {
                unsigned long long ad = pk2(av[i], av[i]);
#pragma unroll
                for (int j = 0; j < 4; j++) acc2[i][j] = fma2(ad, bp[j], acc2[i][j]);
            }
        }
        __syncthreads();
    }
#pragma unroll
    for (int i = 0; i < 8; i++) {
        int m = bm + tm + i;
#pragma unroll
        for (int j = 0; j < 4; j++) {
            float v0, v1;
            upk2(acc2[i][j], v0, v1);
            int col0 = bn + tn + 2 * j;
            float z0 = v0 - __ldg(th + col0);
            float z1 = v1 - __ldg(th + col0 + 1);
            float s0 = 0.5f * (__fdividef(z0, 1.0f + fabsf(z0)) + 1.0f);
            float s1 = 0.5f * (__fdividef(z1, 1.0f + fabsf(z1)) + 1.0f);
            g_s[(size_t)col0 * BB + m] = s0;
            g_s[(size_t)(col0 + 1) * BB + m] = s1;
        }
    }
}

// ---------------------------------------------------------------------------
// Kernel 3: attn = softmax(relu(x@W1+b1)@W2+b2)  -> g_attn[t][b]
// ---------------------------------------------------------------------------
__global__ __launch_bounds__(256) void k_attn(const float* __restrict__ x,
                                              const float* __restrict__ W1,
                                              const float* __restrict__ b1,
                                              const float* __restrict__ W2,
                                              const float* __restrict__ b2) {
    __shared__ __align__(16) float xst[128 * 32];   // x transposed [k][bl]
    __shared__ __align__(16) float hst[64 * 32];    // h transposed [k][bl]
    __shared__ __align__(16) float stage[128 * 33]; // W chunks / logits
    int tid = threadIdx.x;
    int b0 = blockIdx.x * 32;
#pragma unroll
    for (int j = 0; j < 4; j++) {
        int idx = tid + 256 * j;            // 1024 float4
        int bl = idx & 31;
        int kq = (idx >> 5) * 4;
        float4 v = *(const float4*)(x + (size_t)(b0 + bl) * 128 + kq);
        xst[(kq + 0) * 32 + bl] = v.x; xst[(kq + 1) * 32 + bl] = v.y;
        xst[(kq + 2) * 32 + bl] = v.z; xst[(kq + 3) * 32 + bl] = v.w;
    }
    int bl = tid & 31;
    int grp = tid >> 5;   // warp id, 0..7
    // phase 2: h = relu(x@W1+b1), each thread 8 h-values (4 f32x2 pairs)
    unsigned long long hacc2[4] = {0ull, 0ull, 0ull, 0ull};
    for (int kc = 0; kc < 128; kc += 64) {
        __syncthreads();
#pragma unroll
        for (int j = 0; j < 4; j++) {
            int idx = tid + 256 * j;        // 4096 floats of W1 chunk
            ((float4*)stage)[idx] = *((const float4*)(W1 + (size_t)kc * 64) + idx);
        }
        __syncthreads();
#pragma unroll 8
        for (int k = 0; k < 64; k++) {
            float xv = xst[(kc + k) * 32 + bl];
            unsigned long long xp = pk2(xv, xv);
            ulonglong2 w0 = *(const ulonglong2*)&stage[k * 64 + grp * 8];
            ulonglong2 w1 = *(const ulonglong2*)&stage[k * 64 + grp * 8 + 4];
            hacc2[0] = fma2(xp, w0.x, hacc2[0]);
            hacc2[1] = fma2(xp, w0.y, hacc2[1]);
            hacc2[2] = fma2(xp, w1.x, hacc2[2]);
            hacc2[3] = fma2(xp, w1.y, hacc2[3]);
        }
    }
#pragma unroll
    for (int jj = 0; jj < 4; jj++) {
        float h0, h1;
        upk2(hacc2[jj], h0, h1);
        h0 += __ldg(b1 + grp * 8 + 2 * jj);
        h1 += __ldg(b1 + grp * 8 + 2 * jj + 1);
        hst[(grp * 8 + 2 * jj) * 32 + bl] = fmaxf(h0, 0.f);
        hst[(grp * 8 + 2 * jj + 1) * 32 + bl] = fmaxf(h1, 0.f);
    }
    // phase 3: logits = h@W2+b2, each thread 16 t-values (8 pairs)
    unsigned long long lacc2[8];
#pragma unroll
    for (int j = 0; j < 8; j++) lacc2[j] = 0ull;
    for (int kc = 0; kc < 64; kc += 32) {
        __syncthreads();
#pragma unroll
        for (int j = 0; j < 4; j++) {
            int idx = tid + 256 * j;        // 4096 floats of W2 chunk
            ((float4*)stage)[idx] = *((const float4*)(W2 + (size_t)kc * 128) + idx);
        }
        __syncthreads();
#pragma unroll 4
        for (int k = 0; k < 32; k++) {
            float hv = hst[(kc + k) * 32 + bl];
            unsigned long long hp = pk2(hv, hv);
            const ulonglong2* wr = (const ulonglong2*)&stage[k * 128 + grp * 16];
            ulonglong2 q0 = wr[0], q1 = wr[1], q2 = wr[2], q3 = wr[3];
            lacc2[0] = fma2(hp, q0.x, lacc2[0]); lacc2[1] = fma2(hp, q0.y, lacc2[1]);
            lacc2[2] = fma2(hp, q1.x, lacc2[2]); lacc2[3] = fma2(hp, q1.y, lacc2[3]);
            lacc2[4] = fma2(hp, q2.x, lacc2[4]); lacc2[5] = fma2(hp, q2.y, lacc2[5]);
            lacc2[6] = fma2(hp, q3.x, lacc2[6]); lacc2[7] = fma2(hp, q3.y, lacc2[7]);
        }
    }
    __syncthreads();
#pragma unroll
    for (int jj = 0; jj < 8; jj++) {
        float l0, l1;
        upk2(lacc2[jj], l0, l1);
        stage[(grp * 16 + 2 * jj) * 33 + bl] = l0 + __ldg(b2 + grp * 16 + 2 * jj);
        stage[(grp * 16 + 2 * jj + 1) * 33 + bl] = l1 + __ldg(b2 + grp * 16 + 2 * jj + 1);
    }
    __syncthreads();
    int lane = bl;
    for (int r4 = 0; r4 < 4; r4++) {
        int r = grp * 4 + r4;
        float v0 = stage[(lane +  0) * 33 + r];
        float v1 = stage[(lane + 32) * 33 + r];
        float v2 = stage[(lane + 64) * 33 + r];
        float v3 = stage[(lane + 96) * 33 + r];
        float m = fmaxf(fmaxf(v0, v1), fmaxf(v2, v3));
#pragma unroll
        for (int o = 16; o > 0; o >>= 1) m = fmaxf(m, __shfl_xor_sync(0xffffffffu, m, o));
        float e0 = __expf(v0 - m), e1 = __expf(v1 - m), e2 = __expf(v2 - m), e3 = __expf(v3 - m);
        float s = e0 + e1 + e2 + e3;
#pragma unroll
        for (int o = 16; o > 0; o >>= 1) s += __shfl_xor_sync(0xffffffffu, s, o);
        float inv = __fdividef(1.f, s);
        int gb = b0 + r;
        g_attn[(size_t)(lane +  0) * BB + gb] = e0 * inv;
        g_attn[(size_t)(lane + 32) * BB + gb] = e1 * inv;
        g_attn[(size_t)(lane + 64) * BB + gb] = e2 * inv;
        g_attn[(size_t)(lane + 96) * BB + gb] = e3 * inv;
    }
}

// ---------------------------------------------------------------------------
// Kernel 4: tree evaluation (f32x2 class pairs). Block = 256 b x TPG trees.
// ---------------------------------------------------------------------------
__global__ __launch_bounds__(256) void k_trees() {
    __shared__ __align__(16) float lps[LL * 12];   // one tree's leaf probs
    int tid = threadIdx.x;
    int b = blockIdx.x * 256 + tid;
    int tg = blockIdx.y;
    unsigned long long acc2[5] = {0ull, 0ull, 0ull, 0ull, 0ull};

    for (int ti = 0; ti < TPG; ti++) {
        int t = tg * TPG + ti;
        __syncthreads();
        const float4* src = (const float4*)(g_lp + (size_t)t * LL * 12);
        for (int i = tid; i < 384; i += 256) ((float4*)lps)[i] = src[i];
        __syncthreads();

        const float* sp = g_s + (size_t)t * DD * BB + b;   // coalesced
        float s0 = sp[0],      s1 = sp[BB],     s2 = sp[2 * BB], s3 = sp[3 * BB];
        float s4 = sp[4 * BB], s5 = sp[5 * BB], s6 = sp[6 * BB];
        float a = g_attn[(size_t)t * BB + b];

        unsigned long long plo[8];
#pragma unroll
        for (int j = 0; j < 8; j++) {
            float v = (j & 1) ? (1.f - s0) : s0;
            v *= (j & 2) ? (1.f - s1) : s1;
            v *= (j & 4) ? (1.f - s2) : s2;
            plo[j] = pk2(v, v);
        }
        float hi16[16];
#pragma unroll
        for (int j = 0; j < 16; j++) {
            float v = (j & 1) ? (1.f - s3) : s3;
            v *= (j & 2) ? (1.f - s4) : s4;
            v *= (j & 4) ? (1.f - s5) : s5;
            v *= (j & 8) ? (1.f - s6) : s6;
            hi16[j] = v * a;   // fold attention weight
        }
#pragma unroll 4
        for (int hi = 0; hi < 16; hi++) {
            unsigned long long ph2 = pk2(hi16[hi], hi16[hi]);
            const float* rowb = lps + hi * 96;
#pragma unroll
            for (int lo = 0; lo < 8; lo++) {
                unsigned long long pl = mul2(ph2, plo[lo]);
                const float* row = rowb + lo * 12;
                ulonglong2 q0 = *(const ulonglong2*)(row);        // c0..c3
                ulonglong2 q1 = *(const ulonglong2*)(row + 4);    // c4..c7
                unsigned long long q2 = *(const unsigned long long*)(row + 8); // c8,c9
                acc2[0] = fma2(pl, q0.x, acc2[0]);
                acc2[1] = fma2(pl, q0.y, acc2[1]);
                acc2[2] = fma2(pl, q1.x, acc2[2]);
                acc2[3] = fma2(pl, q1.y, acc2[3]);
                acc2[4] = fma2(pl, q2,   acc2[4]);
            }
        }
    }
    float* po = g_partial + ((size_t)tg * BB + b) * CC;
#pragma unroll
    for (int j = 0; j < 5; j++) {
        float v0, v1;
        upk2(acc2[j], v0, v1);
        po[2 * j] = v0;
        po[2 * j + 1] = v1;
    }
}

// ---------------------------------------------------------------------------
// Kernel 5: reduce NG partials -> output
// ---------------------------------------------------------------------------
__global__ void k_reduce(float* __restrict__ out) {
    int i = blockIdx.x * 256 + threadIdx.x;
    if (i < BB * CC) {
        float v = 0.f;
#pragma unroll
        for (int g = 0; g < NG; g++) v += g_partial[(size_t)g * BB * CC + i];
        out[i] = v;
    }
}

// ---------------------------------------------------------------------------
extern "C" void kernel_launch(void* const* d_in, const int* in_sizes, int n_in,
                              void* d_out, int out_size) {
    const float* x    = (const float*)d_in[0];
    const float* fm   = (const float*)d_in[1];
    const float* th   = (const float*)d_in[2];
    const float* leaf = (const float*)d_in[3];
    const float* W1   = (const float*)d_in[4];
    const float* b1   = (const float*)d_in[5];
    const float* W2   = (const float*)d_in[6];
    const float* b2   = (const float*)d_in[7];
    float* out = (float*)d_out;

    k_leafsm<<<64, 256>>>(leaf);
    k_zs<<<dim3(64, 7), 256>>>(x, fm, th);
    k_attn<<<256, 256>>>(x, W1, b1, W2, b2);
    k_trees<<<dim3(32, NG), 256>>>();
    k_reduce<<<320, 256>>>(out);
}

// round 4
// speedup vs baseline: 1.0720x; 1.0630x over previous
#include <cuda_runtime.h>
#include <cstdint>
#include <math.h>

#define BB 8192
#define TT 128
#define DD 7
#define CC 10
#define LL 128
#define NCOL (TT*DD)   // 896
#define NGR 2          // tree halves

// Scratch (device globals: allocation-free rule)
__device__ __align__(16) float g_s[(size_t)NCOL*BB];      // s[col][b]
__device__ __align__(16) float g_attn[(size_t)TT*BB];     // attn[t][b]
__device__ __align__(16) float g_lpf[TT*16*32*4];         // B fragments: [t][ks][lane]{b0n0,b1n0,b0n1,b1n1}
__device__ __align__(16) float g_partial[(size_t)NGR*BB*CC];

// ---- packed fp32x2 helpers ------------------------------------------------
__device__ __forceinline__ unsigned long long pk2(float lo, float hi) {
    unsigned long long r;
    asm("mov.b64 %0, {%1, %2};" : "=l"(r) : "f"(lo), "f"(hi));
    return r;
}
__device__ __forceinline__ void upk2(unsigned long long v, float& lo, float& hi) {
    asm("mov.b64 {%0, %1}, %2;" : "=f"(lo), "=f"(hi) : "l"(v));
}
__device__ __forceinline__ unsigned long long fma2(unsigned long long a,
                                                   unsigned long long b,
                                                   unsigned long long c) {
    unsigned long long d;
    asm("fma.rn.f32x2 %0, %1, %2, %3;" : "=l"(d) : "l"(a), "l"(b), "l"(c));
    return d;
}

// ---- tf32 helpers ----------------------------------------------------------
__device__ __forceinline__ float rna_tf32(float x) {
    float o;
    asm("cvt.rna.tf32.f32 %0, %1;" : "=f"(o) : "f"(x));
    return o;
}
__device__ __forceinline__ void mma_tf32(float* c, uint32_t a0, uint32_t a1,
                                         uint32_t a2, uint32_t a3,
                                         uint32_t b0, uint32_t b1) {
    asm volatile(
        "mma.sync.aligned.m16n8k8.row.col.f32.tf32.tf32.f32 "
        "{%0,%1,%2,%3}, {%4,%5,%6,%7}, {%8,%9}, {%0,%1,%2,%3};"
        : "+f"(c[0]), "+f"(c[1]), "+f"(c[2]), "+f"(c[3])
        : "r"(a0), "r"(a1), "r"(a2), "r"(a3), "r"(b0), "r"(b1));
}

// ---------------------------------------------------------------------------
// Kernel 1: leaf softmax -> B fragments (tf32-RNA) in mma.sync layout.
// One thread per (tree t, leaf l).  l = ks*8 + kk; this row feeds lane
// (gid*4 + (kk&3)), register slot kk>>2, for every n-column gid.
// ---------------------------------------------------------------------------
__global__ void k_leafprep(const float* __restrict__ leaf) {
    int row = blockIdx.x * 256 + threadIdx.x;
    if (row >= TT * LL) return;
    int t = row >> 7, l = row & 127;
    const float* in = leaf + (size_t)row * CC;
    float m = in[0];
#pragma unroll
    for (int c = 1; c < CC; c++) m = fmaxf(m, in[c]);
    float e[CC]; float sum = 0.f;
#pragma unroll
    for (int c = 0; c < CC; c++) { e[c] = __expf(in[c] - m); sum += e[c]; }
    float inv = __fdividef(1.f, sum);
    float lp[CC];
#pragma unroll
    for (int c = 0; c < CC; c++) lp[c] = rna_tf32(e[c] * inv);

    int ks = l >> 3, kk = l & 7, tg = kk & 3, slot = kk >> 2;
    float* base = g_lpf + (size_t)((t * 16 + ks) * 32) * 4;
#pragma unroll
    for (int gid = 0; gid < 8; gid++) {
        float* o = base + (gid * 4 + tg) * 4;
        o[slot] = lp[gid];                               // n-tile 0: class gid
        o[2 + slot] = (gid < 2) ? lp[8 + gid] : 0.f;     // n-tile 1: class 8+gid
    }
}

// ---------------------------------------------------------------------------
// Kernel 2: z = x @ FM^T - th, s = 0.5*(z/(1+|z|)+1)  -> g_s[col][b]
// ---------------------------------------------------------------------------
__global__ __launch_bounds__(256) void k_zs(const float* __restrict__ x,
                                            const float* __restrict__ fm,
                                            const float* __restrict__ th) {
    __shared__ __align__(16) float As[32][128];
    __shared__ __align__(16) float Bs[32][128];
    int tid = threadIdx.x;
    int bm = blockIdx.x * 128;
    int bn = blockIdx.y * 128;
    int tm = (tid >> 4) * 8;
    int tn = (tid & 15) * 8;
    unsigned long long acc2[8][4];
#pragma unroll
    for (int i = 0; i < 8; i++)
#pragma unroll
        for (int j = 0; j < 4; j++) acc2[i][j] = 0ull;

    for (int kc = 0; kc < 128; kc += 32) {
#pragma unroll
        for (int j = 0; j < 4; j++) {
            int fl = tid + 256 * j;
            int row = fl >> 3;
            int kq = (fl & 7) * 4;
            float4 v = *(const float4*)(x + (size_t)(bm + row) * 128 + kc + kq);
            As[kq + 0][row] = v.x; As[kq + 1][row] = v.y;
            As[kq + 2][row] = v.z; As[kq + 3][row] = v.w;
            float4 w = *(const float4*)(fm + (size_t)(bn + row) * 128 + kc + kq);
            Bs[kq + 0][row] = w.x; Bs[kq + 1][row] = w.y;
            Bs[kq + 2][row] = w.z; Bs[kq + 3][row] = w.w;
        }
        __syncthreads();
#pragma unroll
        for (int k = 0; k < 32; k++) {
            float4 a0 = *(const float4*)&As[k][tm];
            float4 a1 = *(const float4*)&As[k][tm + 4];
            ulonglong2 bq0 = *(const ulonglong2*)&Bs[k][tn];
            ulonglong2 bq1 = *(const ulonglong2*)&Bs[k][tn + 4];
            unsigned long long bp[4] = {bq0.x, bq0.y, bq1.x, bq1.y};
            float av[8] = {a0.x, a0.y, a0.z, a0.w, a1.x, a1.y, a1.z, a1.w};
#pragma unroll
            for (int i = 0; i < 8; i++) {
                unsigned long long ad = pk2(av[i], av[i]);
#pragma unroll
                for (int j = 0; j < 4; j++) acc2[i][j] = fma2(ad, bp[j], acc2[i][j]);
            }
        }
        __syncthreads();
    }
#pragma unroll
    for (int i = 0; i < 8; i++) {
        int m = bm + tm + i;
#pragma unroll
        for (int j = 0; j < 4; j++) {
            float v0, v1;
            upk2(acc2[i][j], v0, v1);
            int col0 = bn + tn + 2 * j;
            float z0 = v0 - __ldg(th + col0);
            float z1 = v1 - __ldg(th + col0 + 1);
            g_s[(size_t)col0 * BB + m] = 0.5f * (__fdividef(z0, 1.0f + fabsf(z0)) + 1.0f);
            g_s[(size_t)(col0 + 1) * BB + m] = 0.5f * (__fdividef(z1, 1.0f + fabsf(z1)) + 1.0f);
        }
    }
}

// ---------------------------------------------------------------------------
// Kernel 3: attn = softmax(relu(x@W1+b1)@W2+b2)  -> g_attn[t][b]
// ---------------------------------------------------------------------------
__global__ __launch_bounds__(256) void k_attn(const float* __restrict__ x,
                                              const float* __restrict__ W1,
                                              const float* __restrict__ b1,
                                              const float* __restrict__ W2,
                                              const float* __restrict__ b2) {
    __shared__ __align__(16) float xst[128 * 32];
    __shared__ __align__(16) float hst[64 * 32];
    __shared__ __align__(16) float stage[128 * 33];
    int tid = threadIdx.x;
    int b0 = blockIdx.x * 32;
#pragma unroll
    for (int j = 0; j < 4; j++) {
        int idx = tid + 256 * j;
        int bl = idx & 31;
        int kq = (idx >> 5) * 4;
        float4 v = *(const float4*)(x + (size_t)(b0 + bl) * 128 + kq);
        xst[(kq + 0) * 32 + bl] = v.x; xst[(kq + 1) * 32 + bl] = v.y;
        xst[(kq + 2) * 32 + bl] = v.z; xst[(kq + 3) * 32 + bl] = v.w;
    }
    int bl = tid & 31;
    int grp = tid >> 5;
    unsigned long long hacc2[4] = {0ull, 0ull, 0ull, 0ull};
    for (int kc = 0; kc < 128; kc += 64) {
        __syncthreads();
#pragma unroll
        for (int j = 0; j < 4; j++) {
            int idx = tid + 256 * j;
            ((float4*)stage)[idx] = *((const float4*)(W1 + (size_t)kc * 64) + idx);
        }
        __syncthreads();
#pragma unroll 8
        for (int k = 0; k < 64; k++) {
            float xv = xst[(kc + k) * 32 + bl];
            unsigned long long xp = pk2(xv, xv);
            ulonglong2 w0 = *(const ulonglong2*)&stage[k * 64 + grp * 8];
            ulonglong2 w1 = *(const ulonglong2*)&stage[k * 64 + grp * 8 + 4];
            hacc2[0] = fma2(xp, w0.x, hacc2[0]);
            hacc2[1] = fma2(xp, w0.y, hacc2[1]);
            hacc2[2] = fma2(xp, w1.x, hacc2[2]);
            hacc2[3] = fma2(xp, w1.y, hacc2[3]);
        }
    }
#pragma unroll
    for (int jj = 0; jj < 4; jj++) {
        float h0, h1;
        upk2(hacc2[jj], h0, h1);
        h0 += __ldg(b1 + grp * 8 + 2 * jj);
        h1 += __ldg(b1 + grp * 8 + 2 * jj + 1);
        hst[(grp * 8 + 2 * jj) * 32 + bl] = fmaxf(h0, 0.f);
        hst[(grp * 8 + 2 * jj + 1) * 32 + bl] = fmaxf(h1, 0.f);
    }
    unsigned long long lacc2[8];
#pragma unroll
    for (int j = 0; j < 8; j++) lacc2[j] = 0ull;
    for (int kc = 0; kc < 64; kc += 32) {
        __syncthreads();
#pragma unroll
        for (int j = 0; j < 4; j++) {
            int idx = tid + 256 * j;
            ((float4*)stage)[idx] = *((const float4*)(W2 + (size_t)kc * 128) + idx);
        }
        __syncthreads();
#pragma unroll 4
        for (int k = 0; k < 32; k++) {
            float hv = hst[(kc + k) * 32 + bl];
            unsigned long long hp = pk2(hv, hv);
            const ulonglong2* wr = (const ulonglong2*)&stage[k * 128 + grp * 16];
            ulonglong2 q0 = wr[0], q1 = wr[1], q2 = wr[2], q3 = wr[3];
            lacc2[0] = fma2(hp, q0.x, lacc2[0]); lacc2[1] = fma2(hp, q0.y, lacc2[1]);
            lacc2[2] = fma2(hp, q1.x, lacc2[2]); lacc2[3] = fma2(hp, q1.y, lacc2[3]);
            lacc2[4] = fma2(hp, q2.x, lacc2[4]); lacc2[5] = fma2(hp, q2.y, lacc2[5]);
            lacc2[6] = fma2(hp, q3.x, lacc2[6]); lacc2[7] = fma2(hp, q3.y, lacc2[7]);
        }
    }
    __syncthreads();
#pragma unroll
    for (int jj = 0; jj < 8; jj++) {
        float l0, l1;
        upk2(lacc2[jj], l0, l1);
        stage[(grp * 16 + 2 * jj) * 33 + bl] = l0 + __ldg(b2 + grp * 16 + 2 * jj);
        stage[(grp * 16 + 2 * jj + 1) * 33 + bl] = l1 + __ldg(b2 + grp * 16 + 2 * jj + 1);
    }
    __syncthreads();
    int lane = bl;
    for (int r4 = 0; r4 < 4; r4++) {
        int r = grp * 4 + r4;
        float v0 = stage[(lane +  0) * 33 + r];
        float v1 = stage[(lane + 32) * 33 + r];
        float v2 = stage[(lane + 64) * 33 + r];
        float v3 = stage[(lane + 96) * 33 + r];
        float m = fmaxf(fmaxf(v0, v1), fmaxf(v2, v3));
#pragma unroll
        for (int o = 16; o > 0; o >>= 1) m = fmaxf(m, __shfl_xor_sync(0xffffffffu, m, o));
        float e0 = __expf(v0 - m), e1 = __expf(v1 - m), e2 = __expf(v2 - m), e3 = __expf(v3 - m);
        float s = e0 + e1 + e2 + e3;
#pragma unroll
        for (int o = 16; o > 0; o >>= 1) s += __shfl_xor_sync(0xffffffffu, s, o);
        float inv = __fdividef(1.f, s);
        int gb = b0 + r;
        g_attn[(size_t)(lane +  0) * BB + gb] = e0 * inv;
        g_attn[(size_t)(lane + 32) * BB + gb] = e1 * inv;
        g_attn[(size_t)(lane + 64) * BB + gb] = e2 * inv;
        g_attn[(size_t)(lane + 96) * BB + gb] = e3 * inv;
    }
}

// ---------------------------------------------------------------------------
// Kernel 4: tree evaluation via mma.sync m16n8k8 tf32.
// Warp tile: 16 batch rows x 16 classes over K=128 leaves (16 k-steps x 2 n).
// A = P fragment built in registers from split-sigmoid factors (attn folded).
// Block = 128 threads = 4 warps = 64 batch rows; grid (128, NGR halves).
// ---------------------------------------------------------------------------
__global__ __launch_bounds__(128) void k_trees_mma() {
    int tid = threadIdx.x;
    int warp = tid >> 5, lane = tid & 31;
    int gid = lane >> 2, tg = lane & 3;
    int r0 = blockIdx.x * 64 + warp * 16 + gid;   // A row 0; row 1 = r0+8
    int r1 = r0 + 8;
    int t0 = blockIdx.y * 64;

    float c0[4] = {0.f, 0.f, 0.f, 0.f};   // classes 0..7
    float c1[4] = {0.f, 0.f, 0.f, 0.f};   // classes 8..15 (only 8,9 real)

#pragma unroll 1
    for (int j = 0; j < 64; j++) {
        int t = t0 + j;
        const float* sp = g_s + (size_t)t * DD * BB;
        float sA[DD], sB[DD];
#pragma unroll
        for (int d = 0; d < DD; d++) {
            sA[d] = __ldg(sp + (size_t)d * BB + r0);
            sB[d] = __ldg(sp + (size_t)d * BB + r1);
        }
        float aA = __ldg(g_attn + (size_t)t * BB + r0);
        float aB = __ldg(g_attn + (size_t)t * BB + r1);

        // lo factors at columns tg and tg+4 (bit2 of col selects s2 side)
        float pA = ((tg & 1) ? (1.f - sA[0]) : sA[0]) * ((tg & 2) ? (1.f - sA[1]) : sA[1]);
        float pB = ((tg & 1) ? (1.f - sB[0]) : sB[0]) * ((tg & 2) ? (1.f - sB[1]) : sB[1]);
        float loA0 = pA * sA[2], loA1 = pA * (1.f - sA[2]);
        float loB0 = pB * sB[2], loB1 = pB * (1.f - sB[2]);

        // hi16 per row, attn folded at the root
        float hA[16], hB[16];
        {
            float h2a0 = aA * sA[3], h2a1 = aA * (1.f - sA[3]);
            float h2b0 = aB * sB[3], h2b1 = aB * (1.f - sB[3]);
            float h4a[4], h4b[4];
#pragma unroll
            for (int i = 0; i < 4; i++) {
                float f4a = (i & 2) ? (1.f - sA[4]) : sA[4];
                float f4b = (i & 2) ? (1.f - sB[4]) : sB[4];
                h4a[i] = ((i & 1) ? h2a1 : h2a0) * f4a;
                h4b[i] = ((i & 1) ? h2b1 : h2b0) * f4b;
            }
#pragma unroll
            for (int i = 0; i < 16; i++) {
                float f5a = (i & 4) ? (1.f - sA[5]) : sA[5];
                float f5b = (i & 4) ? (1.f - sB[5]) : sB[5];
                float f6a = (i & 8) ? (1.f - sA[6]) : sA[6];
                float f6b = (i & 8) ? (1.f - sB[6]) : sB[6];
                hA[i] = h4a[i & 3] * f5a * f6a;
                hB[i] = h4b[i & 3] * f5b * f6b;
            }
        }

        const float4* bp = (const float4*)g_lpf + (size_t)(t * 16) * 32 + lane;
#pragma unroll
        for (int ks = 0; ks < 16; ks++) {
            float4 bf = __ldg(&bp[ks * 32]);
            uint32_t a0 = __float_as_uint(rna_tf32(hA[ks] * loA0));
            uint32_t a1 = __float_as_uint(rna_tf32(hB[ks] * loB0));
            uint32_t a2 = __float_as_uint(rna_tf32(hA[ks] * loA1));
            uint32_t a3 = __float_as_uint(rna_tf32(hB[ks] * loB1));
            mma_tf32(c0, a0, a1, a2, a3, __float_as_uint(bf.x), __float_as_uint(bf.y));
            mma_tf32(c1, a0, a1, a2, a3, __float_as_uint(bf.z), __float_as_uint(bf.w));
        }
    }

    float* po0 = g_partial + ((size_t)blockIdx.y * BB + r0) * CC;
    float* po1 = g_partial + ((size_t)blockIdx.y * BB + r1) * CC;
    po0[tg * 2] = c0[0]; po0[tg * 2 + 1] = c0[1];
    po1[tg * 2] = c0[2]; po1[tg * 2 + 1] = c0[3];
    if (tg == 0) {
        po0[8] = c1[0]; po0[9] = c1[1];
        po1[8] = c1[2]; po1[9] = c1[3];
    }
}

// ---------------------------------------------------------------------------
// Kernel 5: reduce NGR partials -> output
// ---------------------------------------------------------------------------
__global__ void k_reduce(float* __restrict__ out) {
    int i = blockIdx.x * 256 + threadIdx.x;
    if (i < BB * CC)
        out[i] = g_partial[i] + g_partial[(size_t)BB * CC + i];
}

// ---------------------------------------------------------------------------
extern "C" void kernel_launch(void* const* d_in, const int* in_sizes, int n_in,
                              void* d_out, int out_size) {
    const float* x    = (const float*)d_in[0];
    const float* fm   = (const float*)d_in[1];
    const float* th   = (const float*)d_in[2];
    const float* leaf = (const float*)d_in[3];
    const float* W1   = (const float*)d_in[4];
    const float* b1   = (const float*)d_in[5];
    const float* W2   = (const float*)d_in[6];
    const float* b2   = (const float*)d_in[7];
    float* out = (float*)d_out;

    k_leafprep<<<64, 256>>>(leaf);
    k_zs<<<dim3(64, 7), 256>>>(x, fm, th);
    k_attn<<<256, 256>>>(x, W1, b1, W2, b2);
    k_trees_mma<<<dim3(128, NGR), 128>>>();
    k_reduce<<<320, 256>>>(out);
}

// round 6
// speedup vs baseline: 1.2539x; 1.1696x over previous
#include <cuda_runtime.h>
#include <cstdint>
#include <math.h>

#define BB 8192
#define TT 128
#define DD 7
#define CC 10
#define LL 128
#define NCOL (TT*DD)   // 896
#define NGR 8          // tree groups
#define TPG (TT/NGR)   // 16 trees per group

// Scratch (device globals: allocation-free rule)
__device__ __align__(16) float g_s[(size_t)NCOL*BB];      // s[col][b]
__device__ __align__(16) float g_attn[(size_t)TT*BB];     // attn[t][b]
__device__ __align__(16) float g_lpf[TT*16*32*4];         // B fragments: [t][ks][lane]{b0n0,b1n0,b0n1,b1n1}
__device__ __align__(16) float g_partial[(size_t)NGR*BB*CC];

// ---- packed fp32x2 helpers ------------------------------------------------
__device__ __forceinline__ unsigned long long pk2(float lo, float hi) {
    unsigned long long r;
    asm("mov.b64 %0, {%1, %2};" : "=l"(r) : "f"(lo), "f"(hi));
    return r;
}
__device__ __forceinline__ void upk2(unsigned long long v, float& lo, float& hi) {
    asm("mov.b64 {%0, %1}, %2;" : "=f"(lo), "=f"(hi) : "l"(v));
}
__device__ __forceinline__ unsigned long long fma2(unsigned long long a,
                                                   unsigned long long b,
                                                   unsigned long long c) {
    unsigned long long d;
    asm("fma.rn.f32x2 %0, %1, %2, %3;" : "=l"(d) : "l"(a), "l"(b), "l"(c));
    return d;
}

// ---- tf32 helpers ----------------------------------------------------------
__device__ __forceinline__ float rna_tf32(float x) {
    float o;
    asm("cvt.rna.tf32.f32 %0, %1;" : "=f"(o) : "f"(x));
    return o;
}
__device__ __forceinline__ void mma_tf32(float* c, uint32_t a0, uint32_t a1,
                                         uint32_t a2, uint32_t a3,
                                         uint32_t b0, uint32_t b1) {
    asm volatile(
        "mma.sync.aligned.m16n8k8.row.col.f32.tf32.tf32.f32 "
        "{%0,%1,%2,%3}, {%4,%5,%6,%7}, {%8,%9}, {%0,%1,%2,%3};"
        : "+f"(c[0]), "+f"(c[1]), "+f"(c[2]), "+f"(c[3])
        : "r"(a0), "r"(a1), "r"(a2), "r"(a3), "r"(b0), "r"(b1));
}

// ---------------------------------------------------------------------------
// Kernel 1: leaf softmax -> B fragments (tf32-RNA) in mma.sync layout.
// ---------------------------------------------------------------------------
__global__ void k_leafprep(const float* __restrict__ leaf) {
    int row = blockIdx.x * 256 + threadIdx.x;
    if (row >= TT * LL) return;
    int t = row >> 7, l = row & 127;
    const float* in = leaf + (size_t)row * CC;
    float m = in[0];
#pragma unroll
    for (int c = 1; c < CC; c++) m = fmaxf(m, in[c]);
    float e[CC]; float sum = 0.f;
#pragma unroll
    for (int c = 0; c < CC; c++) { e[c] = __expf(in[c] - m); sum += e[c]; }
    float inv = __fdividef(1.f, sum);
    float lp[CC];
#pragma unroll
    for (int c = 0; c < CC; c++) lp[c] = rna_tf32(e[c] * inv);

    int ks = l >> 3, kk = l & 7, tg = kk & 3, slot = kk >> 2;
    float* base = g_lpf + (size_t)((t * 16 + ks) * 32) * 4;
#pragma unroll
    for (int gid = 0; gid < 8; gid++) {
        float* o = base + (gid * 4 + tg) * 4;
        o[slot] = lp[gid];                               // n-tile 0: class gid
        o[2 + slot] = (gid < 2) ? lp[8 + gid] : 0.f;     // n-tile 1: class 8+gid
    }
}

// ---------------------------------------------------------------------------
// Kernel 2: z = x @ FM^T - th, s = 0.5*(z/(1+|z|)+1)  -> g_s[col][b]
// ---------------------------------------------------------------------------
__global__ __launch_bounds__(256) void k_zs(const float* __restrict__ x,
                                            const float* __restrict__ fm,
                                            const float* __restrict__ th) {
    __shared__ __align__(16) float As[32][128];
    __shared__ __align__(16) float Bs[32][128];
    int tid = threadIdx.x;
    int bm = blockIdx.x * 128;
    int bn = blockIdx.y * 128;
    int tm = (tid >> 4) * 8;
    int tn = (tid & 15) * 8;
    unsigned long long acc2[8][4];
#pragma unroll
    for (int i = 0; i < 8; i++)
#pragma unroll
        for (int j = 0; j < 4; j++) acc2[i][j] = 0ull;

    for (int kc = 0; kc < 128; kc += 32) {
#pragma unroll
        for (int j = 0; j < 4; j++) {
            int fl = tid + 256 * j;
            int row = fl >> 3;
            int kq = (fl & 7) * 4;
            float4 v = *(const float4*)(x + (size_t)(bm + row) * 128 + kc + kq);
            As[kq + 0][row] = v.x; As[kq + 1][row] = v.y;
            As[kq + 2][row] = v.z; As[kq + 3][row] = v.w;
            float4 w = *(const float4*)(fm + (size_t)(bn + row) * 128 + kc + kq);
            Bs[kq + 0][row] = w.x; Bs[kq + 1][row] = w.y;
            Bs[kq + 2][row] = w.z; Bs[kq + 3][row] = w.w;
        }
        __syncthreads();
#pragma unroll
        for (int k = 0; k < 32; k++) {
            float4 a0 = *(const float4*)&As[k][tm];
            float4 a1 = *(const float4*)&As[k][tm + 4];
            ulonglong2 bq0 = *(const ulonglong2*)&Bs[k][tn];
            ulonglong2 bq1 = *(const ulonglong2*)&Bs[k][tn + 4];
            unsigned long long bp[4] = {bq0.x, bq0.y, bq1.x, bq1.y};
            float av[8] = {a0.x, a0.y, a0.z, a0.w, a1.x, a1.y, a1.z, a1.w};
#pragma unroll
            for (int i = 0; i < 8; i++) {
                unsigned long long ad = pk2(av[i], av[i]);
#pragma unroll
                for (int j = 0; j < 4; j++) acc2[i][j] = fma2(ad, bp[j], acc2[i][j]);
            }
        }
        __syncthreads();
    }
#pragma unroll
    for (int i = 0; i < 8; i++) {
        int m = bm + tm + i;
#pragma unroll
        for (int j = 0; j < 4; j++) {
            float v0, v1;
            upk2(acc2[i][j], v0, v1);
            int col0 = bn + tn + 2 * j;
            float z0 = v0 - __ldg(th + col0);
            float z1 = v1 - __ldg(th + col0 + 1);
            g_s[(size_t)col0 * BB + m] = 0.5f * (__fdividef(z0, 1.0f + fabsf(z0)) + 1.0f);
            g_s[(size_t)(col0 + 1) * BB + m] = 0.5f * (__fdividef(z1, 1.0f + fabsf(z1)) + 1.0f);
        }
    }
}

// ---------------------------------------------------------------------------
// Kernel 3: attn = softmax(relu(x@W1+b1)@W2+b2)  -> g_attn[t][b]
// ---------------------------------------------------------------------------
__global__ __launch_bounds__(256) void k_attn(const float* __restrict__ x,
                                              const float* __restrict__ W1,
                                              const float* __restrict__ b1,
                                              const float* __restrict__ W2,
                                              const float* __restrict__ b2) {
    __shared__ __align__(16) float xst[128 * 32];
    __shared__ __align__(16) float hst[64 * 32];
    __shared__ __align__(16) float stage[128 * 33];
    int tid = threadIdx.x;
    int b0 = blockIdx.x * 32;
#pragma unroll
    for (int j = 0; j < 4; j++) {
        int idx = tid + 256 * j;
        int bl = idx & 31;
        int kq = (idx >> 5) * 4;
        float4 v = *(const float4*)(x + (size_t)(b0 + bl) * 128 + kq);
        xst[(kq + 0) * 32 + bl] = v.x; xst[(kq + 1) * 32 + bl] = v.y;
        xst[(kq + 2) * 32 + bl] = v.z; xst[(kq + 3) * 32 + bl] = v.w;
    }
    int bl = tid & 31;
    int grp = tid >> 5;
    unsigned long long hacc2[4] = {0ull, 0ull, 0ull, 0ull};
    for (int kc = 0; kc < 128; kc += 64) {
        __syncthreads();
#pragma unroll
        for (int j = 0; j < 4; j++) {
            int idx = tid + 256 * j;
            ((float4*)stage)[idx] = *((const float4*)(W1 + (size_t)kc * 64) + idx);
        }
        __syncthreads();
#pragma unroll 8
        for (int k = 0; k < 64; k++) {
            float xv = xst[(kc + k) * 32 + bl];
            unsigned long long xp = pk2(xv, xv);
            ulonglong2 w0 = *(const ulonglong2*)&stage[k * 64 + grp * 8];
            ulonglong2 w1 = *(const ulonglong2*)&stage[k * 64 + grp * 8 + 4];
            hacc2[0] = fma2(xp, w0.x, hacc2[0]);
            hacc2[1] = fma2(xp, w0.y, hacc2[1]);
            hacc2[2] = fma2(xp, w1.x, hacc2[2]);
            hacc2[3] = fma2(xp, w1.y, hacc2[3]);
        }
    }
#pragma unroll
    for (int jj = 0; jj < 4; jj++) {
        float h0, h1;
        upk2(hacc2[jj], h0, h1);
        h0 += __ldg(b1 + grp * 8 + 2 * jj);
        h1 += __ldg(b1 + grp * 8 + 2 * jj + 1);
        hst[(grp * 8 + 2 * jj) * 32 + bl] = fmaxf(h0, 0.f);
        hst[(grp * 8 + 2 * jj + 1) * 32 + bl] = fmaxf(h1, 0.f);
    }
    unsigned long long lacc2[8];
#pragma unroll
    for (int j = 0; j < 8; j++) lacc2[j] = 0ull;
    for (int kc = 0; kc < 64; kc += 32) {
        __syncthreads();
#pragma unroll
        for (int j = 0; j < 4; j++) {
            int idx = tid + 256 * j;
            ((float4*)stage)[idx] = *((const float4*)(W2 + (size_t)kc * 128) + idx);
        }
        __syncthreads();
#pragma unroll 4
        for (int k = 0; k < 32; k++) {
            float hv = hst[(kc + k) * 32 + bl];
            unsigned long long hp = pk2(hv, hv);
            const ulonglong2* wr = (const ulonglong2*)&stage[k * 128 + grp * 16];
            ulonglong2 q0 = wr[0], q1 = wr[1], q2 = wr[2], q3 = wr[3];
            lacc2[0] = fma2(hp, q0.x, lacc2[0]); lacc2[1] = fma2(hp, q0.y, lacc2[1]);
            lacc2[2] = fma2(hp, q1.x, lacc2[2]); lacc2[3] = fma2(hp, q1.y, lacc2[3]);
            lacc2[4] = fma2(hp, q2.x, lacc2[4]); lacc2[5] = fma2(hp, q2.y, lacc2[5]);
            lacc2[6] = fma2(hp, q3.x, lacc2[6]); lacc2[7] = fma2(hp, q3.y, lacc2[7]);
        }
    }
    __syncthreads();
#pragma unroll
    for (int jj = 0; jj < 8; jj++) {
        float l0, l1;
        upk2(lacc2[jj], l0, l1);
        stage[(grp * 16 + 2 * jj) * 33 + bl] = l0 + __ldg(b2 + grp * 16 + 2 * jj);
        stage[(grp * 16 + 2 * jj + 1) * 33 + bl] = l1 + __ldg(b2 + grp * 16 + 2 * jj + 1);
    }
    __syncthreads();
    int lane = bl;
    for (int r4 = 0; r4 < 4; r4++) {
        int r = grp * 4 + r4;
        float v0 = stage[(lane +  0) * 33 + r];
        float v1 = stage[(lane + 32) * 33 + r];
        float v2 = stage[(lane + 64) * 33 + r];
        float v3 = stage[(lane + 96) * 33 + r];
        float m = fmaxf(fmaxf(v0, v1), fmaxf(v2, v3));
#pragma unroll
        for (int o = 16; o > 0; o >>= 1) m = fmaxf(m, __shfl_xor_sync(0xffffffffu, m, o));
        float e0 = __expf(v0 - m), e1 = __expf(v1 - m), e2 = __expf(v2 - m), e3 = __expf(v3 - m);
        float s = e0 + e1 + e2 + e3;
#pragma unroll
        for (int o = 16; o > 0; o >>= 1) s += __shfl_xor_sync(0xffffffffu, s, o);
        float inv = __fdividef(1.f, s);
        int gb = b0 + r;
        g_attn[(size_t)(lane +  0) * BB + gb] = e0 * inv;
        g_attn[(size_t)(lane + 32) * BB + gb] = e1 * inv;
        g_attn[(size_t)(lane + 64) * BB + gb] = e2 * inv;
        g_attn[(size_t)(lane + 96) * BB + gb] = e3 * inv;
    }
}

// ---------------------------------------------------------------------------
// Kernel 4: tree evaluation via mma.sync m16n8k8 tf32.
// Block = 256 threads = 8 warps = 128 batch rows; grid (64, NGR).
// Accumulators split by ks-parity -> 4 independent MMA chains per warp.
// ---------------------------------------------------------------------------
__global__ __launch_bounds__(256) void k_trees_mma() {
    int tid = threadIdx.x;
    int warp = tid >> 5, lane = tid & 31;
    int gid = lane >> 2, tg = lane & 3;
    int r0 = blockIdx.x * 128 + warp * 16 + gid;   // A row 0; row 1 = r0+8
    int r1 = r0 + 8;
    int t0 = blockIdx.y * TPG;

    float c0[2][4] = {{0.f,0.f,0.f,0.f},{0.f,0.f,0.f,0.f}};  // classes 0..7, ks parity
    float c1[2][4] = {{0.f,0.f,0.f,0.f},{0.f,0.f,0.f,0.f}};  // classes 8,9

#pragma unroll 1
    for (int j = 0; j < TPG; j++) {
        int t = t0 + j;
        const float* sp = g_s + (size_t)t * DD * BB;
        float sA[DD], sB[DD];
#pragma unroll
        for (int d = 0; d < DD; d++) {
            sA[d] = __ldg(sp + (size_t)d * BB + r0);
            sB[d] = __ldg(sp + (size_t)d * BB + r1);
        }
        float aA = __ldg(g_attn + (size_t)t * BB + r0);
        float aB = __ldg(g_attn + (size_t)t * BB + r1);

        // lo factors at columns tg and tg+4 (bit2 selects s2 side)
        float pA = ((tg & 1) ? (1.f - sA[0]) : sA[0]) * ((tg & 2) ? (1.f - sA[1]) : sA[1]);
        float pB = ((tg & 1) ? (1.f - sB[0]) : sB[0]) * ((tg & 2) ? (1.f - sB[1]) : sB[1]);
        float loA0 = pA * sA[2], loA1 = pA * (1.f - sA[2]);
        float loB0 = pB * sB[2], loB1 = pB * (1.f - sB[2]);

        // hi16[ks] = h4[ks&3] * fq[ks>>2]; attn folded into h4 root
        float h4a[4], h4b[4], fqa[4], fqb[4];
        {
            float h2a0 = aA * sA[3], h2a1 = aA * (1.f - sA[3]);
            float h2b0 = aB * sB[3], h2b1 = aB * (1.f - sB[3]);
#pragma unroll
            for (int i = 0; i < 4; i++) {
                float f4a = (i & 2) ? (1.f - sA[4]) : sA[4];
                float f4b = (i & 2) ? (1.f - sB[4]) : sB[4];
                h4a[i] = ((i & 1) ? h2a1 : h2a0) * f4a;
                h4b[i] = ((i & 1) ? h2b1 : h2b0) * f4b;
                float f5a = (i & 1) ? (1.f - sA[5]) : sA[5];
                float f5b = (i & 1) ? (1.f - sB[5]) : sB[5];
                float f6a = (i & 2) ? (1.f - sA[6]) : sA[6];
                float f6b = (i & 2) ? (1.f - sB[6]) : sB[6];
                fqa[i] = f5a * f6a;
                fqb[i] = f5b * f6b;
            }
        }

        const float4* bp = (const float4*)g_lpf + (size_t)(t * 16) * 32 + lane;
#pragma unroll
        for (int ks = 0; ks < 16; ks++) {
            float4 bf = __ldg(&bp[ks * 32]);
            float hAk = h4a[ks & 3] * fqa[ks >> 2];
            float hBk = h4b[ks & 3] * fqb[ks >> 2];
            uint32_t a0 = __float_as_uint(rna_tf32(hAk * loA0));
            uint32_t a1 = __float_as_uint(rna_tf32(hBk * loB0));
            uint32_t a2 = __float_as_uint(rna_tf32(hAk * loA1));
            uint32_t a3 = __float_as_uint(rna_tf32(hBk * loB1));
            int par = ks & 1;
            mma_tf32(c0[par], a0, a1, a2, a3, __float_as_uint(bf.x), __float_as_uint(bf.y));
            mma_tf32(c1[par], a0, a1, a2, a3, __float_as_uint(bf.z), __float_as_uint(bf.w));
        }
    }

    float* po0 = g_partial + ((size_t)blockIdx.y * BB + r0) * CC;
    float* po1 = g_partial + ((size_t)blockIdx.y * BB + r1) * CC;
    po0[tg * 2]     = c0[0][0] + c0[1][0];
    po0[tg * 2 + 1] = c0[0][1] + c0[1][1];
    po1[tg * 2]     = c0[0][2] + c0[1][2];
    po1[tg * 2 + 1] = c0[0][3] + c0[1][3];
    if (tg == 0) {
        po0[8] = c1[0][0] + c1[1][0]; po0[9] = c1[0][1] + c1[1][1];
        po1[8] = c1[0][2] + c1[1][2]; po1[9] = c1[0][3] + c1[1][3];
    }
}

// ---------------------------------------------------------------------------
// Kernel 5: reduce NGR partials -> output
// ---------------------------------------------------------------------------
__global__ void k_reduce(float* __restrict__ out) {
    int i = blockIdx.x * 256 + threadIdx.x;
    if (i < BB * CC) {
        float v = 0.f;
#pragma unroll
        for (int g = 0; g < NGR; g++) v += g_partial[(size_t)g * BB * CC + i];
        out[i] = v;
    }
}

// ---------------------------------------------------------------------------
extern "C" void kernel_launch(void* const* d_in, const int* in_sizes, int n_in,
                              void* d_out, int out_size) {
    const float* x    = (const float*)d_in[0];
    const float* fm   = (const float*)d_in[1];
    const float* th   = (const float*)d_in[2];
    const float* leaf = (const float*)d_in[3];
    const float* W1   = (const float*)d_in[4];
    const float* b1   = (const float*)d_in[5];
    const float* W2   = (const float*)d_in[6];
    const float* b2   = (const float*)d_in[7];
    float* out = (float*)d_out;

    k_leafprep<<<64, 256>>>(leaf);
    k_zs<<<dim3(64, 7), 256>>>(x, fm, th);
    k_attn<<<256, 256>>>(x, W1, b1, W2, b2);
    k_trees_mma<<<dim3(64, NGR), 256>>>();
    k_reduce<<<320, 256>>>(out);
}

// round 7
// speedup vs baseline: 1.4689x; 1.1715x over previous
#include <cuda_runtime.h>
#include <cstdint>
#include <math.h>

#define BB 8192
#define TT 128
#define DD 7
#define CC 10
#define LL 128
#define NCOL (TT*DD)   // 896
#define NGR 8          // tree groups
#define TPG (TT/NGR)   // 16 trees per group

// Scratch (device globals: allocation-free rule)
__device__ __align__(16) float g_s[(size_t)NCOL*BB];      // s[col][b]
__device__ __align__(16) float g_attn[(size_t)TT*BB];     // attn[t][b]
__device__ __align__(16) float g_lpf[TT*16*32*4];         // B fragments [t][ks][lane]{b0n0,b1n0,b0n1,b1n1}
__device__ __align__(16) float g_partial[(size_t)NGR*BB*CC];

typedef unsigned long long ull;

// ---- packed fp32x2 helpers ------------------------------------------------
__device__ __forceinline__ ull pk2(float lo, float hi) {
    ull r;
    asm("mov.b64 %0, {%1, %2};" : "=l"(r) : "f"(lo), "f"(hi));
    return r;
}
__device__ __forceinline__ void upk2(ull v, float& lo, float& hi) {
    asm("mov.b64 {%0, %1}, %2;" : "=f"(lo), "=f"(hi) : "l"(v));
}
__device__ __forceinline__ ull fma2(ull a, ull b, ull c) {
    ull d;
    asm("fma.rn.f32x2 %0, %1, %2, %3;" : "=l"(d) : "l"(a), "l"(b), "l"(c));
    return d;
}
__device__ __forceinline__ ull mul2(ull a, ull b) {
    ull d;
    asm("mul.rn.f32x2 %0, %1, %2;" : "=l"(d) : "l"(a), "l"(b));
    return d;
}

// ---- tf32 helpers ----------------------------------------------------------
__device__ __forceinline__ float rna_tf32(float x) {
    float o;
    asm("cvt.rna.tf32.f32 %0, %1;" : "=f"(o) : "f"(x));
    return o;
}
__device__ __forceinline__ void mma_tf32(float* c, uint32_t a0, uint32_t a1,
                                         uint32_t a2, uint32_t a3,
                                         uint32_t b0, uint32_t b1) {
    asm volatile(
        "mma.sync.aligned.m16n8k8.row.col.f32.tf32.tf32.f32 "
        "{%0,%1,%2,%3}, {%4,%5,%6,%7}, {%8,%9}, {%0,%1,%2,%3};"
        : "+f"(c[0]), "+f"(c[1]), "+f"(c[2]), "+f"(c[3])
        : "r"(a0), "r"(a1), "r"(a2), "r"(a3), "r"(b0), "r"(b1));
}

// ---------------------------------------------------------------------------
// Kernel 1: leaf softmax -> B fragments (tf32-RNA) in mma.sync layout.
// ---------------------------------------------------------------------------
__global__ void k_leafprep(const float* __restrict__ leaf) {
    int row = blockIdx.x * 256 + threadIdx.x;
    if (row >= TT * LL) return;
    int t = row >> 7, l = row & 127;
    const float* in = leaf + (size_t)row * CC;
    float m = in[0];
#pragma unroll
    for (int c = 1; c < CC; c++) m = fmaxf(m, in[c]);
    float e[CC]; float sum = 0.f;
#pragma unroll
    for (int c = 0; c < CC; c++) { e[c] = __expf(in[c] - m); sum += e[c]; }
    float inv = __fdividef(1.f, sum);
    float lp[CC];
#pragma unroll
    for (int c = 0; c < CC; c++) lp[c] = rna_tf32(e[c] * inv);

    int ks = l >> 3, kk = l & 7, tg = kk & 3, slot = kk >> 2;
    float* base = g_lpf + (size_t)((t * 16 + ks) * 32) * 4;
#pragma unroll
    for (int gid = 0; gid < 8; gid++) {
        float* o = base + (gid * 4 + tg) * 4;
        o[slot] = lp[gid];                               // n-tile 0: class gid
        o[2 + slot] = (gid < 2) ? lp[8 + gid] : 0.f;     // n-tile 1: class 8+gid
    }
}

// ---------------------------------------------------------------------------
// Kernel 2: z = x @ FM^T - th, s = 0.5*(z/(1+|z|)+1)  -> g_s[col][b]
// Split-tf32 mma.sync: z = fm*(x_hi + x_lo), fm exact in tf32.
// Warp tile m32 x n56; block 256 thr = 8 warps = 256 batch rows; grid(32,16).
// ---------------------------------------------------------------------------
__global__ __launch_bounds__(256) void k_zs_mma(const float* __restrict__ x,
                                                const float* __restrict__ fm,
                                                const float* __restrict__ th) {
    int tid = threadIdx.x;
    int warp = tid >> 5, lane = tid & 31;
    int gid = lane >> 2, tg = lane & 3;
    int rbase = blockIdx.x * 256 + warp * 32 + gid;   // rows rbase, +8, +16, +24
    int bn = blockIdx.y * 56;

    float c[2][7][4];
#pragma unroll
    for (int mf = 0; mf < 2; mf++)
#pragma unroll
        for (int nt = 0; nt < 7; nt++)
#pragma unroll
            for (int q = 0; q < 4; q++) c[mf][nt][q] = 0.f;

    const float* xr0 = x + (size_t)rbase * 128;
    const float* xr1 = x + (size_t)(rbase + 8) * 128;
    const float* xr2 = x + (size_t)(rbase + 16) * 128;
    const float* xr3 = x + (size_t)(rbase + 24) * 128;

#pragma unroll
    for (int ks = 0; ks < 16; ks++) {
        int k0 = ks * 8;
        // A fragments (raw x), rows (rbase, +8) and (+16, +24), k = tg, tg+4
        float xv[2][4];
        xv[0][0] = __ldg(xr0 + k0 + tg);     xv[0][1] = __ldg(xr1 + k0 + tg);
        xv[0][2] = __ldg(xr0 + k0 + tg + 4); xv[0][3] = __ldg(xr1 + k0 + tg + 4);
        xv[1][0] = __ldg(xr2 + k0 + tg);     xv[1][1] = __ldg(xr3 + k0 + tg);
        xv[1][2] = __ldg(xr2 + k0 + tg + 4); xv[1][3] = __ldg(xr3 + k0 + tg + 4);
        uint32_t ah[2][4], al[2][4];
#pragma unroll
        for (int mf = 0; mf < 2; mf++)
#pragma unroll
            for (int q = 0; q < 4; q++) {
                float h = rna_tf32(xv[mf][q]);
                ah[mf][q] = __float_as_uint(h);
                al[mf][q] = __float_as_uint(xv[mf][q] - h);  // exact residual
            }
#pragma unroll
        for (int nt = 0; nt < 7; nt++) {
            int col = bn + nt * 8 + gid;
            const float* fp = fm + (size_t)col * 128 + k0;
            uint32_t b0 = __float_as_uint(__ldg(fp + tg));      // 0/1: tf32-exact
            uint32_t b1 = __float_as_uint(__ldg(fp + tg + 4));
#pragma unroll
            for (int mf = 0; mf < 2; mf++) {
                mma_tf32(c[mf][nt], ah[mf][0], ah[mf][1], ah[mf][2], ah[mf][3], b0, b1);
                mma_tf32(c[mf][nt], al[mf][0], al[mf][1], al[mf][2], al[mf][3], b0, b1);
            }
        }
    }

    // epilogue: z -> s, store g_s[col][b]
#pragma unroll
    for (int mf = 0; mf < 2; mf++) {
        int b0r = rbase + mf * 16;
#pragma unroll
        for (int nt = 0; nt < 7; nt++) {
            int col = bn + nt * 8 + tg * 2;
            float t0v = __ldg(th + col), t1v = __ldg(th + col + 1);
            float z0 = c[mf][nt][0] - t0v;
            float z1 = c[mf][nt][1] - t1v;
            float z2 = c[mf][nt][2] - t0v;
            float z3 = c[mf][nt][3] - t1v;
            g_s[(size_t)col * BB + b0r]           = 0.5f * (__fdividef(z0, 1.0f + fabsf(z0)) + 1.0f);
            g_s[(size_t)(col + 1) * BB + b0r]     = 0.5f * (__fdividef(z1, 1.0f + fabsf(z1)) + 1.0f);
            g_s[(size_t)col * BB + b0r + 8]       = 0.5f * (__fdividef(z2, 1.0f + fabsf(z2)) + 1.0f);
            g_s[(size_t)(col + 1) * BB + b0r + 8] = 0.5f * (__fdividef(z3, 1.0f + fabsf(z3)) + 1.0f);
        }
    }
}

// ---------------------------------------------------------------------------
// Kernel 3: attn = softmax(relu(x@W1+b1)@W2+b2)  -> g_attn[t][b]
// ---------------------------------------------------------------------------
__global__ __launch_bounds__(256) void k_attn(const float* __restrict__ x,
                                              const float* __restrict__ W1,
                                              const float* __restrict__ b1,
                                              const float* __restrict__ W2,
                                              const float* __restrict__ b2) {
    __shared__ __align__(16) float xst[128 * 32];
    __shared__ __align__(16) float hst[64 * 32];
    __shared__ __align__(16) float stage[128 * 33];
    int tid = threadIdx.x;
    int b0 = blockIdx.x * 32;
#pragma unroll
    for (int j = 0; j < 4; j++) {
        int idx = tid + 256 * j;
        int bl = idx & 31;
        int kq = (idx >> 5) * 4;
        float4 v = *(const float4*)(x + (size_t)(b0 + bl) * 128 + kq);
        xst[(kq + 0) * 32 + bl] = v.x; xst[(kq + 1) * 32 + bl] = v.y;
        xst[(kq + 2) * 32 + bl] = v.z; xst[(kq + 3) * 32 + bl] = v.w;
    }
    int bl = tid & 31;
    int grp = tid >> 5;
    ull hacc2[4] = {0ull, 0ull, 0ull, 0ull};
    for (int kc = 0; kc < 128; kc += 64) {
        __syncthreads();
#pragma unroll
        for (int j = 0; j < 4; j++) {
            int idx = tid + 256 * j;
            ((float4*)stage)[idx] = *((const float4*)(W1 + (size_t)kc * 64) + idx);
        }
        __syncthreads();
#pragma unroll 8
        for (int k = 0; k < 64; k++) {
            float xv = xst[(kc + k) * 32 + bl];
            ull xp = pk2(xv, xv);
            ulonglong2 w0 = *(const ulonglong2*)&stage[k * 64 + grp * 8];
            ulonglong2 w1 = *(const ulonglong2*)&stage[k * 64 + grp * 8 + 4];
            hacc2[0] = fma2(xp, w0.x, hacc2[0]);
            hacc2[1] = fma2(xp, w0.y, hacc2[1]);
            hacc2[2] = fma2(xp, w1.x, hacc2[2]);
            hacc2[3] = fma2(xp, w1.y, hacc2[3]);
        }
    }
#pragma unroll
    for (int jj = 0; jj < 4; jj++) {
        float h0, h1;
        upk2(hacc2[jj], h0, h1);
        h0 += __ldg(b1 + grp * 8 + 2 * jj);
        h1 += __ldg(b1 + grp * 8 + 2 * jj + 1);
        hst[(grp * 8 + 2 * jj) * 32 + bl] = fmaxf(h0, 0.f);
        hst[(grp * 8 + 2 * jj + 1) * 32 + bl] = fmaxf(h1, 0.f);
    }
    ull lacc2[8];
#pragma unroll
    for (int j = 0; j < 8; j++) lacc2[j] = 0ull;
    for (int kc = 0; kc < 64; kc += 32) {
        __syncthreads();
#pragma unroll
        for (int j = 0; j < 4; j++) {
            int idx = tid + 256 * j;
            ((float4*)stage)[idx] = *((const float4*)(W2 + (size_t)kc * 128) + idx);
        }
        __syncthreads();
#pragma unroll 4
        for (int k = 0; k < 32; k++) {
            float hv = hst[(kc + k) * 32 + bl];
            ull hp = pk2(hv, hv);
            const ulonglong2* wr = (const ulonglong2*)&stage[k * 128 + grp * 16];
            ulonglong2 q0 = wr[0], q1 = wr[1], q2 = wr[2], q3 = wr[3];
            lacc2[0] = fma2(hp, q0.x, lacc2[0]); lacc2[1] = fma2(hp, q0.y, lacc2[1]);
            lacc2[2] = fma2(hp, q1.x, lacc2[2]); lacc2[3] = fma2(hp, q1.y, lacc2[3]);
            lacc2[4] = fma2(hp, q2.x, lacc2[4]); lacc2[5] = fma2(hp, q2.y, lacc2[5]);
            lacc2[6] = fma2(hp, q3.x, lacc2[6]); lacc2[7] = fma2(hp, q3.y, lacc2[7]);
        }
    }
    __syncthreads();
#pragma unroll
    for (int jj = 0; jj < 8; jj++) {
        float l0, l1;
        upk2(lacc2[jj], l0, l1);
        stage[(grp * 16 + 2 * jj) * 33 + bl] = l0 + __ldg(b2 + grp * 16 + 2 * jj);
        stage[(grp * 16 + 2 * jj + 1) * 33 + bl] = l1 + __ldg(b2 + grp * 16 + 2 * jj + 1);
    }
    __syncthreads();
    int lane = bl;
    for (int r4 = 0; r4 < 4; r4++) {
        int r = grp * 4 + r4;
        float v0 = stage[(lane +  0) * 33 + r];
        float v1 = stage[(lane + 32) * 33 + r];
        float v2 = stage[(lane + 64) * 33 + r];
        float v3 = stage[(lane + 96) * 33 + r];
        float m = fmaxf(fmaxf(v0, v1), fmaxf(v2, v3));
#pragma unroll
        for (int o = 16; o > 0; o >>= 1) m = fmaxf(m, __shfl_xor_sync(0xffffffffu, m, o));
        float e0 = __expf(v0 - m), e1 = __expf(v1 - m), e2 = __expf(v2 - m), e3 = __expf(v3 - m);
        float s = e0 + e1 + e2 + e3;
#pragma unroll
        for (int o = 16; o > 0; o >>= 1) s += __shfl_xor_sync(0xffffffffu, s, o);
        float inv = __fdividef(1.f, s);
        int gb = b0 + r;
        g_attn[(size_t)(lane +  0) * BB + gb] = e0 * inv;
        g_attn[(size_t)(lane + 32) * BB + gb] = e1 * inv;
        g_attn[(size_t)(lane + 64) * BB + gb] = e2 * inv;
        g_attn[(size_t)(lane + 96) * BB + gb] = e3 * inv;
    }
}

// ---------------------------------------------------------------------------
// Kernel 4: tree eval via mma.sync tf32. Packed f32x2 A-fragment build
// (row pair = operand pair), raw-bit A (HW truncates), next-tree prefetch.
// ---------------------------------------------------------------------------
__global__ __launch_bounds__(256) void k_trees_mma() {
    int tid = threadIdx.x;
    int warp = tid >> 5, lane = tid & 31;
    int gid = lane >> 2, tg = lane & 3;
    int r0 = blockIdx.x * 128 + warp * 16 + gid;
    int r1 = r0 + 8;
    int t0 = blockIdx.y * TPG;

    float c0[2][4] = {{0.f,0.f,0.f,0.f},{0.f,0.f,0.f,0.f}};
    float c1[2][4] = {{0.f,0.f,0.f,0.f},{0.f,0.f,0.f,0.f}};

    const ull one = pk2(1.f, 1.f);
    const ull mone = pk2(-1.f, -1.f);

    // preload tree t0
    float sA[DD], sB[DD], aA, aB;
    {
        const float* sp = g_s + (size_t)t0 * DD * BB;
#pragma unroll
        for (int d = 0; d < DD; d++) {
            sA[d] = __ldg(sp + (size_t)d * BB + r0);
            sB[d] = __ldg(sp + (size_t)d * BB + r1);
        }
        aA = __ldg(g_attn + (size_t)t0 * BB + r0);
        aB = __ldg(g_attn + (size_t)t0 * BB + r1);
    }

#pragma unroll 1
    for (int j = 0; j < TPG; j++) {
        int t = t0 + j;
        // prefetch next tree (overlaps with mma loop below)
        float sAn[DD], sBn[DD], aAn, aBn;
        if (j + 1 < TPG) {
            const float* sp = g_s + (size_t)(t + 1) * DD * BB;
#pragma unroll
            for (int d = 0; d < DD; d++) {
                sAn[d] = __ldg(sp + (size_t)d * BB + r0);
                sBn[d] = __ldg(sp + (size_t)d * BB + r1);
            }
            aAn = __ldg(g_attn + (size_t)(t + 1) * BB + r0);
            aBn = __ldg(g_attn + (size_t)(t + 1) * BB + r1);
        }

        // packed (rowA, rowB) factor build
        ull s0 = pk2(sA[0], sB[0]), s1 = pk2(sA[1], sB[1]), s2 = pk2(sA[2], sB[2]);
        ull s3 = pk2(sA[3], sB[3]), s4 = pk2(sA[4], sB[4]);
        ull s5 = pk2(sA[5], sB[5]), s6 = pk2(sA[6], sB[6]);
        ull aP = pk2(aA, aB);

        ull f0 = (tg & 1) ? fma2(s0, mone, one) : s0;
        ull f1 = (tg & 2) ? fma2(s1, mone, one) : s1;
        ull p = mul2(f0, f1);
        ull lo0 = mul2(p, s2);
        ull lo1 = mul2(p, fma2(s2, mone, one));

        ull h2_0 = mul2(aP, s3);
        ull h2_1 = mul2(aP, fma2(s3, mone, one));
        ull n4 = fma2(s4, mone, one);
        ull n5 = fma2(s5, mone, one);
        ull n6 = fma2(s6, mone, one);
        ull h4[4], fq[4];
        h4[0] = mul2(h2_0, s4); h4[1] = mul2(h2_1, s4);
        h4[2] = mul2(h2_0, n4); h4[3] = mul2(h2_1, n4);
        fq[0] = mul2(s5, s6); fq[1] = mul2(n5, s6);
        fq[2] = mul2(s5, n6); fq[3] = mul2(n5, n6);

        const float4* bp = (const float4*)g_lpf + (size_t)(t * 16) * 32 + lane;
#pragma unroll
        for (int ks = 0; ks < 16; ks++) {
            float4 bf = __ldg(&bp[ks * 32]);
            ull hk = mul2(h4[ks & 3], fq[ks >> 2]);
            ull a01 = mul2(hk, lo0);     // (a0=rowA*lo0, a1=rowB*lo0)
            ull a23 = mul2(hk, lo1);     // (a2=rowA*lo1, a3=rowB*lo1)
            float fa0, fa1, fa2, fa3;
            upk2(a01, fa0, fa1);
            upk2(a23, fa2, fa3);
            int par = ks & 1;
            mma_tf32(c0[par], __float_as_uint(fa0), __float_as_uint(fa1),
                     __float_as_uint(fa2), __float_as_uint(fa3),
                     __float_as_uint(bf.x), __float_as_uint(bf.y));
            mma_tf32(c1[par], __float_as_uint(fa0), __float_as_uint(fa1),
                     __float_as_uint(fa2), __float_as_uint(fa3),
                     __float_as_uint(bf.z), __float_as_uint(bf.w));
        }

        if (j + 1 < TPG) {
#pragma unroll
            for (int d = 0; d < DD; d++) { sA[d] = sAn[d]; sB[d] = sBn[d]; }
            aA = aAn; aB = aBn;
        }
    }

    float* po0 = g_partial + ((size_t)blockIdx.y * BB + r0) * CC;
    float* po1 = g_partial + ((size_t)blockIdx.y * BB + r1) * CC;
    po0[tg * 2]     = c0[0][0] + c0[1][0];
    po0[tg * 2 + 1] = c0[0][1] + c0[1][1];
    po1[tg * 2]     = c0[0][2] + c0[1][2];
    po1[tg * 2 + 1] = c0[0][3] + c0[1][3];
    if (tg == 0) {
        po0[8] = c1[0][0] + c1[1][0]; po0[9] = c1[0][1] + c1[1][1];
        po1[8] = c1[0][2] + c1[1][2]; po1[9] = c1[0][3] + c1[1][3];
    }
}

// ---------------------------------------------------------------------------
// Kernel 5: reduce NGR partials -> output
// ---------------------------------------------------------------------------
__global__ void k_reduce(float* __restrict__ out) {
    int i = blockIdx.x * 256 + threadIdx.x;
    if (i < BB * CC) {
        float v = 0.f;
#pragma unroll
        for (int g = 0; g < NGR; g++) v += g_partial[(size_t)g * BB * CC + i];
        out[i] = v;
    }
}

// ---------------------------------------------------------------------------
extern "C" void kernel_launch(void* const* d_in, const int* in_sizes, int n_in,
                              void* d_out, int out_size) {
    const float* x    = (const float*)d_in[0];
    const float* fm   = (const float*)d_in[1];
    const float* th   = (const float*)d_in[2];
    const float* leaf = (const float*)d_in[3];
    const float* W1   = (const float*)d_in[4];
    const float* b1   = (const float*)d_in[5];
    const float* W2   = (const float*)d_in[6];
    const float* b2   = (const float*)d_in[7];
    float* out = (float*)d_out;

    k_leafprep<<<64, 256>>>(leaf);
    k_zs_mma<<<dim3(32, 16), 256>>>(x, fm, th);
    k_attn<<<256, 256>>>(x, W1, b1, W2, b2);
    k_trees_mma<<<dim3(64, NGR), 256>>>();
    k_reduce<<<320, 256>>>(out);
}

// round 8
// speedup vs baseline: 1.7505x; 1.1917x over previous
#include <cuda_runtime.h>
#include <cstdint>
#include <math.h>

#define BB 8192
#define TT 128
#define DD 7
#define CC 10
#define LL 128
#define NCOL (TT*DD)   // 896
#define NGR 16         // tree groups
#define TPG (TT/NGR)   // 8 trees per group

// Scratch (device globals: allocation-free rule)
__device__ __align__(16) float g_s[(size_t)NCOL*BB];      // s[col][b]
__device__ __align__(16) float g_attn[(size_t)TT*BB];     // attn[t][b]
__device__ __align__(16) float g_lpf[TT*16*32*4];         // B fragments [t][ks][lane]{b0n0,b1n0,b0n1,b1n1}
__device__ __align__(16) float g_partial[(size_t)NGR*BB*CC];

typedef unsigned long long ull;

// ---- packed fp32x2 helpers ------------------------------------------------
__device__ __forceinline__ ull pk2(float lo, float hi) {
    ull r;
    asm("mov.b64 %0, {%1, %2};" : "=l"(r) : "f"(lo), "f"(hi));
    return r;
}
__device__ __forceinline__ void upk2(ull v, float& lo, float& hi) {
    asm("mov.b64 {%0, %1}, %2;" : "=f"(lo), "=f"(hi) : "l"(v));
}
__device__ __forceinline__ ull fma2(ull a, ull b, ull c) {
    ull d;
    asm("fma.rn.f32x2 %0, %1, %2, %3;" : "=l"(d) : "l"(a), "l"(b), "l"(c));
    return d;
}
__device__ __forceinline__ ull mul2(ull a, ull b) {
    ull d;
    asm("mul.rn.f32x2 %0, %1, %2;" : "=l"(d) : "l"(a), "l"(b));
    return d;
}

// ---- tf32 helpers ----------------------------------------------------------
__device__ __forceinline__ float rna_tf32(float x) {
    float o;
    asm("cvt.rna.tf32.f32 %0, %1;" : "=f"(o) : "f"(x));
    return o;
}
__device__ __forceinline__ void mma_tf32(float* c, uint32_t a0, uint32_t a1,
                                         uint32_t a2, uint32_t a3,
                                         uint32_t b0, uint32_t b1) {
    asm volatile(
        "mma.sync.aligned.m16n8k8.row.col.f32.tf32.tf32.f32 "
        "{%0,%1,%2,%3}, {%4,%5,%6,%7}, {%8,%9}, {%0,%1,%2,%3};"
        : "+f"(c[0]), "+f"(c[1]), "+f"(c[2]), "+f"(c[3])
        : "r"(a0), "r"(a1), "r"(a2), "r"(a3), "r"(b0), "r"(b1));
}

// ---------------------------------------------------------------------------
// Kernel 1: leaf softmax -> B fragments (tf32-RNA) in mma.sync layout.
// ---------------------------------------------------------------------------
__global__ void k_leafprep(const float* __restrict__ leaf) {
    int row = blockIdx.x * 256 + threadIdx.x;
    if (row >= TT * LL) return;
    int t = row >> 7, l = row & 127;
    const float* in = leaf + (size_t)row * CC;
    float m = in[0];
#pragma unroll
    for (int c = 1; c < CC; c++) m = fmaxf(m, in[c]);
    float e[CC]; float sum = 0.f;
#pragma unroll
    for (int c = 0; c < CC; c++) { e[c] = __expf(in[c] - m); sum += e[c]; }
    float inv = __fdividef(1.f, sum);
    float lp[CC];
#pragma unroll
    for (int c = 0; c < CC; c++) lp[c] = rna_tf32(e[c] * inv);

    int ks = l >> 3, kk = l & 7, tg = kk & 3, slot = kk >> 2;
    float* base = g_lpf + (size_t)((t * 16 + ks) * 32) * 4;
#pragma unroll
    for (int gid = 0; gid < 8; gid++) {
        float* o = base + (gid * 4 + tg) * 4;
        o[slot] = lp[gid];                               // n-tile 0: class gid
        o[2 + slot] = (gid < 2) ? lp[8 + gid] : 0.f;     // n-tile 1: class 8+gid
    }
}

// ---------------------------------------------------------------------------
// Kernel 2: z = x @ FM^T - th, s = 0.5*(z/(1+|z|)+1)  -> g_s[col][b]
// Split-tf32 mma.sync: z = fm*(x_hi + x_lo), fm exact in tf32.
// ---------------------------------------------------------------------------
__global__ __launch_bounds__(256) void k_zs_mma(const float* __restrict__ x,
                                                const float* __restrict__ fm,
                                                const float* __restrict__ th) {
    int tid = threadIdx.x;
    int warp = tid >> 5, lane = tid & 31;
    int gid = lane >> 2, tg = lane & 3;
    int rbase = blockIdx.x * 256 + warp * 32 + gid;   // rows rbase, +8, +16, +24
    int bn = blockIdx.y * 56;

    float c[2][7][4];
#pragma unroll
    for (int mf = 0; mf < 2; mf++)
#pragma unroll
        for (int nt = 0; nt < 7; nt++)
#pragma unroll
            for (int q = 0; q < 4; q++) c[mf][nt][q] = 0.f;

    const float* xr0 = x + (size_t)rbase * 128;
    const float* xr1 = x + (size_t)(rbase + 8) * 128;
    const float* xr2 = x + (size_t)(rbase + 16) * 128;
    const float* xr3 = x + (size_t)(rbase + 24) * 128;

#pragma unroll
    for (int ks = 0; ks < 16; ks++) {
        int k0 = ks * 8;
        float xv[2][4];
        xv[0][0] = __ldg(xr0 + k0 + tg);     xv[0][1] = __ldg(xr1 + k0 + tg);
        xv[0][2] = __ldg(xr0 + k0 + tg + 4); xv[0][3] = __ldg(xr1 + k0 + tg + 4);
        xv[1][0] = __ldg(xr2 + k0 + tg);     xv[1][1] = __ldg(xr3 + k0 + tg);
        xv[1][2] = __ldg(xr2 + k0 + tg + 4); xv[1][3] = __ldg(xr3 + k0 + tg + 4);
        uint32_t ah[2][4], al[2][4];
#pragma unroll
        for (int mf = 0; mf < 2; mf++)
#pragma unroll
            for (int q = 0; q < 4; q++) {
                float h = rna_tf32(xv[mf][q]);
                ah[mf][q] = __float_as_uint(h);
                al[mf][q] = __float_as_uint(xv[mf][q] - h);  // exact residual
            }
#pragma unroll
        for (int nt = 0; nt < 7; nt++) {
            int col = bn + nt * 8 + gid;
            const float* fp = fm + (size_t)col * 128 + k0;
            uint32_t b0 = __float_as_uint(__ldg(fp + tg));      // 0/1: tf32-exact
            uint32_t b1 = __float_as_uint(__ldg(fp + tg + 4));
#pragma unroll
            for (int mf = 0; mf < 2; mf++) {
                mma_tf32(c[mf][nt], ah[mf][0], ah[mf][1], ah[mf][2], ah[mf][3], b0, b1);
                mma_tf32(c[mf][nt], al[mf][0], al[mf][1], al[mf][2], al[mf][3], b0, b1);
            }
        }
    }

#pragma unroll
    for (int mf = 0; mf < 2; mf++) {
        int b0r = rbase + mf * 16;
#pragma unroll
        for (int nt = 0; nt < 7; nt++) {
            int col = bn + nt * 8 + tg * 2;
            float t0v = __ldg(th + col), t1v = __ldg(th + col + 1);
            float z0 = c[mf][nt][0] - t0v;
            float z1 = c[mf][nt][1] - t1v;
            float z2 = c[mf][nt][2] - t0v;
            float z3 = c[mf][nt][3] - t1v;
            g_s[(size_t)col * BB + b0r]           = 0.5f * (__fdividef(z0, 1.0f + fabsf(z0)) + 1.0f);
            g_s[(size_t)(col + 1) * BB + b0r]     = 0.5f * (__fdividef(z1, 1.0f + fabsf(z1)) + 1.0f);
            g_s[(size_t)col * BB + b0r + 8]       = 0.5f * (__fdividef(z2, 1.0f + fabsf(z2)) + 1.0f);
            g_s[(size_t)(col + 1) * BB + b0r + 8] = 0.5f * (__fdividef(z3, 1.0f + fabsf(z3)) + 1.0f);
        }
    }
}

// ---------------------------------------------------------------------------
// Kernel 3: attn = softmax(relu(x@W1+b1)@W2+b2)  -> g_attn[t][b]
// ---------------------------------------------------------------------------
__global__ __launch_bounds__(256) void k_attn(const float* __restrict__ x,
                                              const float* __restrict__ W1,
                                              const float* __restrict__ b1,
                                              const float* __restrict__ W2,
                                              const float* __restrict__ b2) {
    __shared__ __align__(16) float xst[128 * 32];
    __shared__ __align__(16) float hst[64 * 32];
    __shared__ __align__(16) float stage[128 * 33];
    int tid = threadIdx.x;
    int b0 = blockIdx.x * 32;
#pragma unroll
    for (int j = 0; j < 4; j++) {
        int idx = tid + 256 * j;
        int bl = idx & 31;
        int kq = (idx >> 5) * 4;
        float4 v = *(const float4*)(x + (size_t)(b0 + bl) * 128 + kq);
        xst[(kq + 0) * 32 + bl] = v.x; xst[(kq + 1) * 32 + bl] = v.y;
        xst[(kq + 2) * 32 + bl] = v.z; xst[(kq + 3) * 32 + bl] = v.w;
    }
    int bl = tid & 31;
    int grp = tid >> 5;
    ull hacc2[4] = {0ull, 0ull, 0ull, 0ull};
    for (int kc = 0; kc < 128; kc += 64) {
        __syncthreads();
#pragma unroll
        for (int j = 0; j < 4; j++) {
            int idx = tid + 256 * j;
            ((float4*)stage)[idx] = *((const float4*)(W1 + (size_t)kc * 64) + idx);
        }
        __syncthreads();
#pragma unroll 8
        for (int k = 0; k < 64; k++) {
            float xv = xst[(kc + k) * 32 + bl];
            ull xp = pk2(xv, xv);
            ulonglong2 w0 = *(const ulonglong2*)&stage[k * 64 + grp * 8];
            ulonglong2 w1 = *(const ulonglong2*)&stage[k * 64 + grp * 8 + 4];
            hacc2[0] = fma2(xp, w0.x, hacc2[0]);
            hacc2[1] = fma2(xp, w0.y, hacc2[1]);
            hacc2[2] = fma2(xp, w1.x, hacc2[2]);
            hacc2[3] = fma2(xp, w1.y, hacc2[3]);
        }
    }
#pragma unroll
    for (int jj = 0; jj < 4; jj++) {
        float h0, h1;
        upk2(hacc2[jj], h0, h1);
        h0 += __ldg(b1 + grp * 8 + 2 * jj);
        h1 += __ldg(b1 + grp * 8 + 2 * jj + 1);
        hst[(grp * 8 + 2 * jj) * 32 + bl] = fmaxf(h0, 0.f);
        hst[(grp * 8 + 2 * jj + 1) * 32 + bl] = fmaxf(h1, 0.f);
    }
    ull lacc2[8];
#pragma unroll
    for (int j = 0; j < 8; j++) lacc2[j] = 0ull;
    for (int kc = 0; kc < 64; kc += 32) {
        __syncthreads();
#pragma unroll
        for (int j = 0; j < 4; j++) {
            int idx = tid + 256 * j;
            ((float4*)stage)[idx] = *((const float4*)(W2 + (size_t)kc * 128) + idx);
        }
        __syncthreads();
#pragma unroll 4
        for (int k = 0; k < 32; k++) {
            float hv = hst[(kc + k) * 32 + bl];
            ull hp = pk2(hv, hv);
            const ulonglong2* wr = (const ulonglong2*)&stage[k * 128 + grp * 16];
            ulonglong2 q0 = wr[0], q1 = wr[1], q2 = wr[2], q3 = wr[3];
            lacc2[0] = fma2(hp, q0.x, lacc2[0]); lacc2[1] = fma2(hp, q0.y, lacc2[1]);
            lacc2[2] = fma2(hp, q1.x, lacc2[2]); lacc2[3] = fma2(hp, q1.y, lacc2[3]);
            lacc2[4] = fma2(hp, q2.x, lacc2[4]); lacc2[5] = fma2(hp, q2.y, lacc2[5]);
            lacc2[6] = fma2(hp, q3.x, lacc2[6]); lacc2[7] = fma2(hp, q3.y, lacc2[7]);
        }
    }
    __syncthreads();
#pragma unroll
    for (int jj = 0; jj < 8; jj++) {
        float l0, l1;
        upk2(lacc2[jj], l0, l1);
        stage[(grp * 16 + 2 * jj) * 33 + bl] = l0 + __ldg(b2 + grp * 16 + 2 * jj);
        stage[(grp * 16 + 2 * jj + 1) * 33 + bl] = l1 + __ldg(b2 + grp * 16 + 2 * jj + 1);
    }
    __syncthreads();
    int lane = bl;
    for (int r4 = 0; r4 < 4; r4++) {
        int r = grp * 4 + r4;
        float v0 = stage[(lane +  0) * 33 + r];
        float v1 = stage[(lane + 32) * 33 + r];
        float v2 = stage[(lane + 64) * 33 + r];
        float v3 = stage[(lane + 96) * 33 + r];
        float m = fmaxf(fmaxf(v0, v1), fmaxf(v2, v3));
#pragma unroll
        for (int o = 16; o > 0; o >>= 1) m = fmaxf(m, __shfl_xor_sync(0xffffffffu, m, o));
        float e0 = __expf(v0 - m), e1 = __expf(v1 - m), e2 = __expf(v2 - m), e3 = __expf(v3 - m);
        float s = e0 + e1 + e2 + e3;
#pragma unroll
        for (int o = 16; o > 0; o >>= 1) s += __shfl_xor_sync(0xffffffffu, s, o);
        float inv = __fdividef(1.f, s);
        int gb = b0 + r;
        g_attn[(size_t)(lane +  0) * BB + gb] = e0 * inv;
        g_attn[(size_t)(lane + 32) * BB + gb] = e1 * inv;
        g_attn[(size_t)(lane + 64) * BB + gb] = e2 * inv;
        g_attn[(size_t)(lane + 96) * BB + gb] = e3 * inv;
    }
}

// ---------------------------------------------------------------------------
// Kernel 4: tree eval via mma.sync tf32.
// 3 blocks/SM (reg cap), 4-way ks-parity chains on c0, no prefetch regs.
// ---------------------------------------------------------------------------
__global__ __launch_bounds__(256, 3) void k_trees_mma() {
    int tid = threadIdx.x;
    int warp = tid >> 5, lane = tid & 31;
    int gid = lane >> 2, tg = lane & 3;
    int r0 = blockIdx.x * 128 + warp * 16 + gid;
    int r1 = r0 + 8;
    int t0 = blockIdx.y * TPG;

    float c0[4][4] = {{0.f,0.f,0.f,0.f},{0.f,0.f,0.f,0.f},
                      {0.f,0.f,0.f,0.f},{0.f,0.f,0.f,0.f}};   // classes 0..7, ks mod 4
    float c1[2][4] = {{0.f,0.f,0.f,0.f},{0.f,0.f,0.f,0.f}};   // classes 8,9, ks parity

    const ull one = pk2(1.f, 1.f);
    const ull mone = pk2(-1.f, -1.f);

#pragma unroll 1
    for (int j = 0; j < TPG; j++) {
        int t = t0 + j;
        const float* sp = g_s + (size_t)t * DD * BB;
        float sA[DD], sB[DD];
#pragma unroll
        for (int d = 0; d < DD; d++) {
            sA[d] = __ldg(sp + (size_t)d * BB + r0);
            sB[d] = __ldg(sp + (size_t)d * BB + r1);
        }
        float aA = __ldg(g_attn + (size_t)t * BB + r0);
        float aB = __ldg(g_attn + (size_t)t * BB + r1);

        // packed (rowA, rowB) factor build
        ull s0 = pk2(sA[0], sB[0]), s1 = pk2(sA[1], sB[1]), s2 = pk2(sA[2], sB[2]);
        ull s3 = pk2(sA[3], sB[3]), s4 = pk2(sA[4], sB[4]);
        ull s5 = pk2(sA[5], sB[5]), s6 = pk2(sA[6], sB[6]);
        ull aP = pk2(aA, aB);

        ull f0 = (tg & 1) ? fma2(s0, mone, one) : s0;
        ull f1 = (tg & 2) ? fma2(s1, mone, one) : s1;
        ull p = mul2(f0, f1);
        ull lo0 = mul2(p, s2);
        ull lo1 = mul2(p, fma2(s2, mone, one));

        ull h2_0 = mul2(aP, s3);
        ull h2_1 = mul2(aP, fma2(s3, mone, one));
        ull n4 = fma2(s4, mone, one);
        ull n5 = fma2(s5, mone, one);
        ull n6 = fma2(s6, mone, one);
        ull h4[4], fq[4];
        h4[0] = mul2(h2_0, s4); h4[1] = mul2(h2_1, s4);
        h4[2] = mul2(h2_0, n4); h4[3] = mul2(h2_1, n4);
        fq[0] = mul2(s5, s6); fq[1] = mul2(n5, s6);
        fq[2] = mul2(s5, n6); fq[3] = mul2(n5, n6);

        const float4* bp = (const float4*)g_lpf + (size_t)(t * 16) * 32 + lane;
#pragma unroll
        for (int ks = 0; ks < 16; ks++) {
            float4 bf = __ldg(&bp[ks * 32]);
            ull hk = mul2(h4[ks & 3], fq[ks >> 2]);
            ull a01 = mul2(hk, lo0);     // (a0=rowA*lo0, a1=rowB*lo0)
            ull a23 = mul2(hk, lo1);     // (a2=rowA*lo1, a3=rowB*lo1)
            float fa0, fa1, fa2, fa3;
            upk2(a01, fa0, fa1);
            upk2(a23, fa2, fa3);
            mma_tf32(c0[ks & 3], __float_as_uint(fa0), __float_as_uint(fa1),
                     __float_as_uint(fa2), __float_as_uint(fa3),
                     __float_as_uint(bf.x), __float_as_uint(bf.y));
            mma_tf32(c1[ks & 1], __float_as_uint(fa0), __float_as_uint(fa1),
                     __float_as_uint(fa2), __float_as_uint(fa3),
                     __float_as_uint(bf.z), __float_as_uint(bf.w));
        }
    }

    float* po0 = g_partial + ((size_t)blockIdx.y * BB + r0) * CC;
    float* po1 = g_partial + ((size_t)blockIdx.y * BB + r1) * CC;
    po0[tg * 2]     = (c0[0][0] + c0[1][0]) + (c0[2][0] + c0[3][0]);
    po0[tg * 2 + 1] = (c0[0][1] + c0[1][1]) + (c0[2][1] + c0[3][1]);
    po1[tg * 2]     = (c0[0][2] + c0[1][2]) + (c0[2][2] + c0[3][2]);
    po1[tg * 2 + 1] = (c0[0][3] + c0[1][3]) + (c0[2][3] + c0[3][3]);
    if (tg == 0) {
        po0[8] = c1[0][0] + c1[1][0]; po0[9] = c1[0][1] + c1[1][1];
        po1[8] = c1[0][2] + c1[1][2]; po1[9] = c1[0][3] + c1[1][3];
    }
}

// ---------------------------------------------------------------------------
// Kernel 5: reduce NGR partials -> output
// ---------------------------------------------------------------------------
__global__ void k_reduce(float* __restrict__ out) {
    int i = blockIdx.x * 256 + threadIdx.x;
    if (i < BB * CC) {
        float v = 0.f;
#pragma unroll
        for (int g = 0; g < NGR; g++) v += g_partial[(size_t)g * BB * CC + i];
        out[i] = v;
    }
}

// ---------------------------------------------------------------------------
extern "C" void kernel_launch(void* const* d_in, const int* in_sizes, int n_in,
                              void* d_out, int out_size) {
    const float* x    = (const float*)d_in[0];
    const float* fm   = (const float*)d_in[1];
    const float* th   = (const float*)d_in[2];
    const float* leaf = (const float*)d_in[3];
    const float* W1   = (const float*)d_in[4];
    const float* b1   = (const float*)d_in[5];
    const float* W2   = (const float*)d_in[6];
    const float* b2   = (const float*)d_in[7];
    float* out = (float*)d_out;

    k_leafprep<<<64, 256>>>(leaf);
    k_zs_mma<<<dim3(32, 16), 256>>>(x, fm, th);
    k_attn<<<256, 256>>>(x, W1, b1, W2, b2);
    k_trees_mma<<<dim3(64, NGR), 256>>>();
    k_reduce<<<320, 256>>>(out);
}